// round 11
// baseline (speedup 1.0000x reference)
#include <cuda_runtime.h>
#include <cuda_fp16.h>
#include <math.h>
#include <stdint.h>

// ---------------------------------------------------------------------------
// MechanismTransformerBlock  B=8 S=1024 D=1024 H=16 DH=64 DFF=4096
// fp16 tensor-core path; hgemm 256x128 CTA tile with 512 threads (16 warps,
// warp tile 32x64 — same per-warp shape & occupancy as the 1222us R8 kernel),
// 3-stage cp.async pipeline; fp16 flash attention; fused add_pe+LN1.
// ---------------------------------------------------------------------------

namespace {
constexpr int Bc = 8, Sc = 1024, Dc = 1024, Hc = 16, DFFc = 4096;
constexpr int BS = Bc * Sc;                       // 8192 rows
constexpr size_t NXD = (size_t)BS * Dc;           // 8,388,608
constexpr int NQKV = 3584;                        // q|k|v|mech-hidden

// fp32 scratch
constexpr size_t OFF_X    = 0;
constexpr size_t OFF_PEP  = OFF_X   + NXD;                    // S x D
constexpr size_t OFF_MECH = OFF_PEP + (size_t)Sc * Dc;        // BS
constexpr size_t OFF_B5   = OFF_MECH+ (size_t)BS;             // D
constexpr size_t OFF_WSM  = OFF_B5  + Dc;                     // 8
constexpr size_t OFF_BQKV = OFF_WSM + 8;                      // 3584
constexpr size_t TOTALF   = OFF_BQKV + NQKV;

// fp16 weight staging offsets (in halfs)
constexpr size_t W16_WI  = 0;
constexpr size_t W16_OW  = W16_WI  + (size_t)Dc * Dc;
constexpr size_t W16_W5  = W16_OW  + (size_t)Dc * Dc;
constexpr size_t W16_FW1 = W16_W5  + (size_t)Dc * Dc;
constexpr size_t W16_FW2 = W16_FW1 + (size_t)Dc * DFFc;
constexpr size_t W16_QKV = W16_FW2 + (size_t)DFFc * Dc;
constexpr size_t W16_TOT = W16_QKV + (size_t)Dc * NQKV;
}

__device__ float  g_buf[TOTALF];
__device__ __half g_h16[NXD];                 // LN output
__device__ __half g_qkv16[(size_t)BS * NQKV]; // q|k|v|mech-hidden
__device__ __half g_ctx16[NXD];               // attention output
__device__ __half g_ffh16[(size_t)BS * DFFc]; // FFN hidden
__device__ __half g_pe16[(size_t)Sc * Dc];
__device__ __half g_w16[W16_TOT];

__device__ __forceinline__ float gelu_exact(float v) {
    return 0.5f * v * (1.0f + erff(v * 0.70710678118654752440f));
}

__device__ __forceinline__ void mma_f16(float* c, const uint32_t* a, uint32_t b0, uint32_t b1) {
    asm volatile(
        "mma.sync.aligned.m16n8k16.row.col.f32.f16.f16.f32 "
        "{%0,%1,%2,%3}, {%4,%5,%6,%7}, {%8,%9}, {%0,%1,%2,%3};\n"
        : "+f"(c[0]), "+f"(c[1]), "+f"(c[2]), "+f"(c[3])
        : "r"(a[0]), "r"(a[1]), "r"(a[2]), "r"(a[3]), "r"(b0), "r"(b1));
}

__device__ __forceinline__ void ldsm_x4(uint32_t& r0, uint32_t& r1, uint32_t& r2, uint32_t& r3,
                                        uint32_t addr) {
    asm volatile("ldmatrix.sync.aligned.m8n8.x4.shared.b16 {%0,%1,%2,%3}, [%4];"
                 : "=r"(r0), "=r"(r1), "=r"(r2), "=r"(r3) : "r"(addr));
}

__device__ __forceinline__ void ldsm_x4t(uint32_t& r0, uint32_t& r1, uint32_t& r2, uint32_t& r3,
                                         uint32_t addr) {
    asm volatile("ldmatrix.sync.aligned.m8n8.x4.trans.shared.b16 {%0,%1,%2,%3}, [%4];"
                 : "=r"(r0), "=r"(r1), "=r"(r2), "=r"(r3) : "r"(addr));
}

__device__ __forceinline__ uint32_t h2bits(float lo, float hi) {
    __half2 h = __floats2half2_rn(lo, hi);
    return *reinterpret_cast<uint32_t*>(&h);
}

__device__ __forceinline__ void cp16(uint32_t smem, const void* g) {
    asm volatile("cp.async.cg.shared.global [%0], [%1], 16;" :: "r"(smem), "l"(g));
}
__device__ __forceinline__ void cp_commit() {
    asm volatile("cp.async.commit_group;");
}
template <int N>
__device__ __forceinline__ void cp_wait() {
    asm volatile("cp.async.wait_group %0;" :: "n"(N));
}

// ---------------------------------------------------------------------------
// fp16 GEMM, 3-stage cp.async pipeline.
// 256x128 CTA tile, BK=16, 512 thr = 16 warps (8M x 2N), warp tile 32x64.
// A smem stage 8KB [m][16] swz c^((m>>2)&1); B stage 4KB [k][128] swz c^(k&7).
// A ring at 0..24KB, B ring at 24..36KB.
// act: 0 none, 1 gelu, 2 gelu iff global col >= 3072.
// Requires M % 256 == 0, N % 128 == 0, K % 16 == 0.
// ---------------------------------------------------------------------------
__global__ void __launch_bounds__(512, 1)
hgemm_k(const __half* __restrict__ A, const __half* __restrict__ Bm,
        const float* __restrict__ bias, const float* __restrict__ resid,
        void* __restrict__ Cv, int M, int N, int K, int act, int outh)
{
    __shared__ __align__(16) unsigned char smem[36864];
    const uint32_t smem_base = (uint32_t)__cvta_generic_to_shared(smem);

    const int tid = threadIdx.x;
    const int w = tid >> 5, l = tid & 31;
    const int wm = (w & 7) * 32;          // warp M offset (8 warps over 256)
    const int wn = (w >> 3) * 64;         // warp N offset (2 warps over 128)
    const int g = l >> 2, t = l & 3;
    const int bn = blockIdx.x, bm = blockIdx.y;
    const __half* Ab = A + (size_t)bm * 256 * K;
    const __half* Bb = Bm + (size_t)bn * 128;

    // A: 256 rows x 2 chunks = 512 chunks, one per thread.
    const int arow = tid >> 1;            // 0..255
    const int ac   = tid & 1;
    const uint32_t a_st = smem_base + arow * 32 + ((ac ^ ((arow >> 2) & 1)) << 4);
    const __half* a_gp = Ab + (size_t)arow * K + ac * 8;
    // B: 16 rows x 16 chunks = 256 chunks, threads 0..255.
    const int brow = tid >> 4;            // 0..31 (only <16 used)
    const int bc   = tid & 15;
    const uint32_t b_st = smem_base + 24576 + brow * 256 + ((bc ^ (brow & 7)) << 4);
    const __half* b_gp = Bb + (size_t)brow * N + bc * 8;
    const bool doB = tid < 256;

    const int amr = ((l >> 3) & 1) * 8 + (l & 7);
    const int acf = l >> 4;
    const int bkk = ((l >> 4) & 1) * 8 + (l & 7);
    const int bcb = (wn >> 3) + ((l >> 3) & 1);

    const int NIT = K >> 4;

    float acc[2][8][4];
#pragma unroll
    for (int i = 0; i < 2; i++)
#pragma unroll
        for (int j = 0; j < 8; j++)
#pragma unroll
            for (int r = 0; r < 4; r++) acc[i][j][r] = 0.f;

    // prologue: stages 0,1
#pragma unroll
    for (int s = 0; s < 2; s++) {
        cp16(a_st + s * 8192, a_gp + s * 16);
        if (doB) cp16(b_st + s * 4096, b_gp + (size_t)(s * 16) * N);
        cp_commit();
    }

    int st = 0;
    for (int it = 0; it < NIT; it++) {
        cp_wait<1>();            // stage it arrived
        __syncthreads();         // stage (it+2)%3 provably drained
        {
            int nx = it + 2;
            if (nx < NIT) {
                int ring = nx - (nx / 3) * 3;
                cp16(a_st + ring * 8192, a_gp + nx * 16);
                if (doB) cp16(b_st + ring * 4096, b_gp + (size_t)(nx * 16) * N);
            }
            cp_commit();
        }
        {
            const uint32_t abuf = smem_base + st * 8192;
            const uint32_t bbuf = smem_base + 24576 + st * 4096;
            uint32_t af[2][4];
#pragma unroll
            for (int i = 0; i < 2; i++) {
                int m = wm + i * 16 + amr;
                uint32_t ad = abuf + m * 32 + ((acf ^ ((m >> 2) & 1)) << 4);
                ldsm_x4(af[i][0], af[i][1], af[i][2], af[i][3], ad);
            }
#pragma unroll
            for (int jp = 0; jp < 4; jp++) {
                int cB = bcb + jp * 2;
                uint32_t bd = bbuf + bkk * 256 + ((cB ^ (bkk & 7)) << 4);
                uint32_t r0, r1, r2, r3;
                ldsm_x4t(r0, r1, r2, r3, bd);
#pragma unroll
                for (int i = 0; i < 2; i++) {
                    mma_f16(acc[i][jp * 2],     af[i], r0, r2);
                    mma_f16(acc[i][jp * 2 + 1], af[i], r1, r3);
                }
            }
        }
        st++; if (st == 3) st = 0;
    }

#pragma unroll
    for (int i = 0; i < 2; i++) {
        int row0 = bm * 256 + wm + i * 16 + g;
        int row1 = row0 + 8;
        size_t ro0 = (size_t)row0 * N;
        size_t ro1 = (size_t)row1 * N;
#pragma unroll
        for (int j = 0; j < 8; j++) {
            int col = bn * 128 + wn + j * 8 + 2 * t;
            float v0 = acc[i][j][0], v1 = acc[i][j][1];
            float v2 = acc[i][j][2], v3 = acc[i][j][3];
            if (bias) {
                float b0 = bias[col], b1 = bias[col + 1];
                v0 += b0; v1 += b1; v2 += b0; v3 += b1;
            }
            bool dg = (act == 1) || (act == 2 && col >= 3072);
            if (dg) {
                v0 = gelu_exact(v0); v1 = gelu_exact(v1);
                v2 = gelu_exact(v2); v3 = gelu_exact(v3);
            }
            if (resid) {
                v0 += resid[ro0 + col]; v1 += resid[ro0 + col + 1];
                v2 += resid[ro1 + col]; v3 += resid[ro1 + col + 1];
            }
            if (outh) {
                __half* C = (__half*)Cv;
                *(uint32_t*)&C[ro0 + col] = h2bits(v0, v1);
                *(uint32_t*)&C[ro1 + col] = h2bits(v2, v3);
            } else {
                float* C = (float*)Cv;
                *(float2*)&C[ro0 + col] = make_float2(v0, v1);
                *(float2*)&C[ro1 + col] = make_float2(v2, v3);
            }
        }
    }
}

// ---------------------------------------------------------------------------
// fp16 flash attention.  QKV fp16 [BS][3584]; mech factor folded into K.
// ---------------------------------------------------------------------------
__device__ __forceinline__ uint32_t aswz(int r, int c) {
    return (uint32_t)(r * 128 + ((c ^ ((r + (r >> 3)) & 7)) << 4));
}

__global__ void __launch_bounds__(256)
attn_h_k(const __half* __restrict__ QKV, const float* __restrict__ mech,
         __half* __restrict__ Octx)
{
    __shared__ __align__(16) __half smem[16384];   // Q 16KB | K 8KB | V 8KB
    const uint32_t sb = (uint32_t)__cvta_generic_to_shared(smem);
    const uint32_t kb = sb + 16384;
    const uint32_t vb = sb + 24576;

    const int tid = threadIdx.x;
    const int w = tid >> 5, l = tid & 31;
    const int g = l >> 2, t = l & 3;
    const int bh = blockIdx.y;
    const int b = bh >> 4, h = bh & 15;
    const int q0 = blockIdx.x * 128;
    const int qr = w * 16;

    {
        int r = tid >> 1;
        int c0 = (tid & 1) * 4;
        const __half* qp = QKV + ((size_t)(b * 1024 + q0 + r)) * NQKV + h * 64;
#pragma unroll
        for (int u = 0; u < 4; u++) {
            int c = c0 + u;
            uint4 v = *(const uint4*)(qp + c * 8);
            asm volatile("st.shared.v4.u32 [%0], {%1,%2,%3,%4};" ::
                         "r"(sb + aswz(r, c)), "r"(v.x), "r"(v.y), "r"(v.z), "r"(v.w));
        }
    }

    float m0 = -1e30f, m1 = -1e30f, l0 = 0.f, l1 = 0.f;
    float acc[8][4];
#pragma unroll
    for (int e = 0; e < 8; e++)
#pragma unroll
        for (int r = 0; r < 4; r++) acc[e][r] = 0.f;
    __syncthreads();

    for (int kt = 0; kt < 16; kt++) {
        const int k0 = kt * 64;
        {
            int r = tid >> 2;
            int c0 = (tid & 3) * 2;
            size_t rowb = ((size_t)(b * 1024 + k0 + r)) * NQKV + h * 64;
            float f = 0.125f * (1.f + mech[(size_t)b * 1024 + k0 + r]);
            __half2 fh = __float2half2_rn(f);
            const __half* kp = QKV + rowb + 1024;
            const __half* vp = QKV + rowb + 2048;
#pragma unroll
            for (int u = 0; u < 2; u++) {
                int c = c0 + u;
                uint4 kv = *(const uint4*)(kp + c * 8);
                __half2* kh = (__half2*)&kv;
                kh[0] = __hmul2(kh[0], fh);
                kh[1] = __hmul2(kh[1], fh);
                kh[2] = __hmul2(kh[2], fh);
                kh[3] = __hmul2(kh[3], fh);
                asm volatile("st.shared.v4.u32 [%0], {%1,%2,%3,%4};" ::
                             "r"(kb + aswz(r, c)), "r"(kv.x), "r"(kv.y), "r"(kv.z), "r"(kv.w));
                uint4 vv = *(const uint4*)(vp + c * 8);
                asm volatile("st.shared.v4.u32 [%0], {%1,%2,%3,%4};" ::
                             "r"(vb + aswz(r, c)), "r"(vv.x), "r"(vv.y), "r"(vv.z), "r"(vv.w));
            }
        }
        __syncthreads();

        float s[8][4];
#pragma unroll
        for (int j = 0; j < 8; j++)
#pragma unroll
            for (int r = 0; r < 4; r++) s[j][r] = 0.f;
#pragma unroll
        for (int kc = 0; kc < 4; kc++) {
            uint32_t a[4];
            {
                int row = qr + (l & 7) + ((l >> 3) & 1) * 8;
                int chunk = 2 * kc + (l >> 4);
                ldsm_x4(a[0], a[1], a[2], a[3], sb + aswz(row, chunk));
            }
#pragma unroll
            for (int jp = 0; jp < 4; jp++) {
                int key = jp * 16 + ((l >> 4) & 1) * 8 + (l & 7);
                int chunk = 2 * kc + ((l >> 3) & 1);
                uint32_t r0, r1, r2, r3;
                ldsm_x4(r0, r1, r2, r3, kb + aswz(key, chunk));
                mma_f16(s[jp * 2],     a, r0, r1);
                mma_f16(s[jp * 2 + 1], a, r2, r3);
            }
        }

        float mx0 = -1e30f, mx1 = -1e30f;
#pragma unroll
        for (int j = 0; j < 8; j++) {
            mx0 = fmaxf(mx0, fmaxf(s[j][0], s[j][1]));
            mx1 = fmaxf(mx1, fmaxf(s[j][2], s[j][3]));
        }
        mx0 = fmaxf(mx0, __shfl_xor_sync(0xffffffffu, mx0, 1));
        mx0 = fmaxf(mx0, __shfl_xor_sync(0xffffffffu, mx0, 2));
        mx1 = fmaxf(mx1, __shfl_xor_sync(0xffffffffu, mx1, 1));
        mx1 = fmaxf(mx1, __shfl_xor_sync(0xffffffffu, mx1, 2));
        float mn0 = fmaxf(m0, mx0), mn1 = fmaxf(m1, mx1);
        float al0 = __expf(m0 - mn0), al1 = __expf(m1 - mn1);
        float sum0 = 0.f, sum1 = 0.f;
#pragma unroll
        for (int j = 0; j < 8; j++) {
            s[j][0] = __expf(s[j][0] - mn0);
            s[j][1] = __expf(s[j][1] - mn0);
            s[j][2] = __expf(s[j][2] - mn1);
            s[j][3] = __expf(s[j][3] - mn1);
            sum0 += s[j][0] + s[j][1];
            sum1 += s[j][2] + s[j][3];
        }
        sum0 += __shfl_xor_sync(0xffffffffu, sum0, 1);
        sum0 += __shfl_xor_sync(0xffffffffu, sum0, 2);
        sum1 += __shfl_xor_sync(0xffffffffu, sum1, 1);
        sum1 += __shfl_xor_sync(0xffffffffu, sum1, 2);
        l0 = l0 * al0 + sum0;
        l1 = l1 * al1 + sum1;
        m0 = mn0; m1 = mn1;
#pragma unroll
        for (int e = 0; e < 8; e++) {
            acc[e][0] *= al0; acc[e][1] *= al0;
            acc[e][2] *= al1; acc[e][3] *= al1;
        }

#pragma unroll
        for (int u = 0; u < 4; u++) {
            uint32_t a[4];
            a[0] = h2bits(s[2 * u][0],     s[2 * u][1]);
            a[1] = h2bits(s[2 * u][2],     s[2 * u][3]);
            a[2] = h2bits(s[2 * u + 1][0], s[2 * u + 1][1]);
            a[3] = h2bits(s[2 * u + 1][2], s[2 * u + 1][3]);
#pragma unroll
            for (int ep = 0; ep < 4; ep++) {
                int key = u * 16 + ((l >> 3) & 1) * 8 + (l & 7);
                int chunk = ep * 2 + (l >> 4);
                uint32_t r0, r1, r2, r3;
                ldsm_x4t(r0, r1, r2, r3, vb + aswz(key, chunk));
                mma_f16(acc[ep * 2],     a, r0, r1);
                mma_f16(acc[ep * 2 + 1], a, r2, r3);
            }
        }
        __syncthreads();
    }

    float inv0 = 1.f / l0, inv1 = 1.f / l1;
    size_t o0 = ((size_t)(b * 1024 + q0 + qr + g)) * 1024 + h * 64;
    size_t o1 = o0 + (size_t)8 * 1024;
#pragma unroll
    for (int e = 0; e < 8; e++) {
        *(uint32_t*)&Octx[o0 + e * 8 + 2 * t] = h2bits(acc[e][0] * inv0, acc[e][1] * inv0);
        *(uint32_t*)&Octx[o1 + e * 8 + 2 * t] = h2bits(acc[e][2] * inv1, acc[e][3] * inv1);
    }
}

// ---------------------------------------------------------------------------
// LayerNorm (1024) -> fp16. One block per row.
// ---------------------------------------------------------------------------
__global__ void layernorm_k(const float* __restrict__ x, const float* __restrict__ g,
                            const float* __restrict__ b, __half* __restrict__ o)
{
    int row = blockIdx.x;
    const float4* xr = (const float4*)(x + (size_t)row * 1024);
    float4 v = xr[threadIdx.x];
    float s  = v.x + v.y + v.z + v.w;
    float ss = fmaf(v.x, v.x, fmaf(v.y, v.y, fmaf(v.z, v.z, v.w * v.w)));
#pragma unroll
    for (int off = 16; off > 0; off >>= 1) {
        s  += __shfl_xor_sync(0xffffffffu, s,  off);
        ss += __shfl_xor_sync(0xffffffffu, ss, off);
    }
    __shared__ float ws[8], wss[8];
    __shared__ float s_mean, s_inv;
    int w = threadIdx.x >> 5, ln = threadIdx.x & 31;
    if (ln == 0) { ws[w] = s; wss[w] = ss; }
    __syncthreads();
    if (threadIdx.x == 0) {
        float S = 0.f, SS = 0.f;
#pragma unroll
        for (int i = 0; i < 8; i++) { S += ws[i]; SS += wss[i]; }
        float mean = S * (1.f / 1024.f);
        float var  = SS * (1.f / 1024.f) - mean * mean;
        s_mean = mean;
        s_inv  = rsqrtf(var + 1e-5f);
    }
    __syncthreads();
    float mean = s_mean, inv = s_inv;
    float4 gv = ((const float4*)g)[threadIdx.x];
    float4 bv = ((const float4*)b)[threadIdx.x];
    uint2 r;
    r.x = h2bits((v.x - mean) * inv * gv.x + bv.x, (v.y - mean) * inv * gv.y + bv.y);
    r.y = h2bits((v.z - mean) * inv * gv.z + bv.z, (v.w - mean) * inv * gv.w + bv.w);
    *(uint2*)&o[(size_t)row * 1024 + threadIdx.x * 4] = r;
}

// Fused: x = x_in + pep (write fp32 residual) AND layernorm(x) -> fp16.
__global__ void ln_addpe_k(const float* __restrict__ xin, const float* __restrict__ pep,
                           const float* __restrict__ g, const float* __restrict__ b,
                           float* __restrict__ xo, __half* __restrict__ o)
{
    int row = blockIdx.x;
    float4 xi = ((const float4*)(xin + (size_t)row * 1024))[threadIdx.x];
    float4 pe = ((const float4*)(pep + (size_t)(row & 1023) * 1024))[threadIdx.x];
    float4 v = make_float4(xi.x + pe.x, xi.y + pe.y, xi.z + pe.z, xi.w + pe.w);
    ((float4*)(xo + (size_t)row * 1024))[threadIdx.x] = v;
    float s  = v.x + v.y + v.z + v.w;
    float ss = fmaf(v.x, v.x, fmaf(v.y, v.y, fmaf(v.z, v.z, v.w * v.w)));
#pragma unroll
    for (int off = 16; off > 0; off >>= 1) {
        s  += __shfl_xor_sync(0xffffffffu, s,  off);
        ss += __shfl_xor_sync(0xffffffffu, ss, off);
    }
    __shared__ float ws[8], wss[8];
    __shared__ float s_mean, s_inv;
    int w = threadIdx.x >> 5, ln = threadIdx.x & 31;
    if (ln == 0) { ws[w] = s; wss[w] = ss; }
    __syncthreads();
    if (threadIdx.x == 0) {
        float S = 0.f, SS = 0.f;
#pragma unroll
        for (int i = 0; i < 8; i++) { S += ws[i]; SS += wss[i]; }
        float mean = S * (1.f / 1024.f);
        float var  = SS * (1.f / 1024.f) - mean * mean;
        s_mean = mean;
        s_inv  = rsqrtf(var + 1e-5f);
    }
    __syncthreads();
    float mean = s_mean, inv = s_inv;
    float4 gv = ((const float4*)g)[threadIdx.x];
    float4 bv = ((const float4*)b)[threadIdx.x];
    uint2 r;
    r.x = h2bits((v.x - mean) * inv * gv.x + bv.x, (v.y - mean) * inv * gv.y + bv.y);
    r.y = h2bits((v.z - mean) * inv * gv.z + bv.z, (v.w - mean) * inv * gv.w + bv.w);
    *(uint2*)&o[(size_t)row * 1024 + threadIdx.x * 4] = r;
}

// ---------------------------------------------------------------------------
// Prep kernels (vectorized)
// ---------------------------------------------------------------------------
__global__ void cvt8_k(const float4* __restrict__ src, uint4* __restrict__ dst, int n8)
{
    int i = blockIdx.x * blockDim.x + threadIdx.x;
    if (i >= n8) return;
    float4 a = src[2 * i], b = src[2 * i + 1];
    dst[i] = make_uint4(h2bits(a.x, a.y), h2bits(a.z, a.w),
                        h2bits(b.x, b.y), h2bits(b.z, b.w));
}

__global__ void build_pe_k(const float* __restrict__ pos, const float* __restrict__ tim,
                           __half* __restrict__ pe)
{
    int i = (blockIdx.x * blockDim.x + threadIdx.x) * 4;   // S*D
    int s = i >> 10, d = i & 1023;
    const float* srcp = (d < 512) ? pos + s * 512 + d : tim + s * 512 + (d - 512);
    float4 v = *(const float4*)srcp;
    *(uint2*)&pe[i] = make_uint2(h2bits(v.x, v.y), h2bits(v.z, v.w));
}

__global__ void softmax5_k(const float* __restrict__ elw, float* __restrict__ wsm,
                           float* __restrict__ out_w)
{
    if (threadIdx.x == 0) {
        float m = elw[0];
        for (int p = 1; p < 5; p++) m = fmaxf(m, elw[p]);
        float e[5], s = 0.f;
        for (int p = 0; p < 5; p++) { e[p] = expf(elw[p] - m); s += e[p]; }
        float inv = 1.f / s;
        for (int p = 0; p < 5; p++) { wsm[p] = e[p] * inv; out_w[p] = e[p] * inv; }
    }
}

__global__ void combine_w5_k(const float* __restrict__ ew, const float* __restrict__ wsm,
                             __half* __restrict__ w5)
{
    int i = (blockIdx.x * blockDim.x + threadIdx.x) * 4;   // D*D
    float w0 = wsm[0], w1 = wsm[1], w2 = wsm[2], w3 = wsm[3], w4 = wsm[4];
    const size_t DD = (size_t)1024 * 1024;
    float4 e0 = *(const float4*)&ew[i];
    float4 e1 = *(const float4*)&ew[DD + i];
    float4 e2 = *(const float4*)&ew[2 * DD + i];
    float4 e3 = *(const float4*)&ew[3 * DD + i];
    float4 e4 = *(const float4*)&ew[4 * DD + i];
    float vx = w0 * e0.x + w1 * e1.x + w2 * e2.x + w3 * e3.x + w4 * e4.x;
    float vy = w0 * e0.y + w1 * e1.y + w2 * e2.y + w3 * e3.y + w4 * e4.y;
    float vz = w0 * e0.z + w1 * e1.z + w2 * e2.z + w3 * e3.z + w4 * e4.z;
    float vw = w0 * e0.w + w1 * e1.w + w2 * e2.w + w3 * e3.w + w4 * e4.w;
    *(uint2*)&w5[i] = make_uint2(h2bits(vx, vy), h2bits(vz, vw));
}

__global__ void combine_b5_k(const float* __restrict__ eb, const float* __restrict__ wsm,
                             float* __restrict__ b5)
{
    int i = blockIdx.x * blockDim.x + threadIdx.x;   // D
    float v = 0.f;
    for (int p = 0; p < 5; p++) v += wsm[p] * eb[p * 1024 + i];
    b5[i] = v;
}

// Pack qw|kw|vw|mw1 -> fp16 [D][3584]; biases -> fp32 [3584]. 8 cols/thread.
__global__ void pack_qkvm_k(const float* __restrict__ qw, const float* __restrict__ kw,
                            const float* __restrict__ vw, const float* __restrict__ mw1,
                            const float* __restrict__ qb, const float* __restrict__ kb,
                            const float* __restrict__ vb, const float* __restrict__ mb1,
                            __half* __restrict__ wq, float* __restrict__ bq)
{
    int i = blockIdx.x * blockDim.x + threadIdx.x;   // D * 448
    int k = i / 448, n = (i - k * 448) * 8;
    const float* sp;
    if (n < 1024)      sp = qw  + k * 1024 + n;
    else if (n < 2048) sp = kw  + k * 1024 + (n - 1024);
    else if (n < 3072) sp = vw  + k * 1024 + (n - 2048);
    else               sp = mw1 + k * 512  + (n - 3072);
    float4 a = *(const float4*)sp;
    float4 b = *(const float4*)(sp + 4);
    *(uint4*)&wq[(size_t)k * NQKV + n] =
        make_uint4(h2bits(a.x, a.y), h2bits(a.z, a.w), h2bits(b.x, b.y), h2bits(b.z, b.w));
    if (i < NQKV) {
        float bb;
        if (i < 1024)      bb = qb[i];
        else if (i < 2048) bb = kb[i - 1024];
        else if (i < 3072) bb = vb[i - 2048];
        else               bb = mb1[i - 3072];
        bq[i] = bb;
    }
}

// mech[r] = sigmoid(dot(qkv16[r, 3072:3584], mw2) + mb2); one warp per row.
__global__ void mech_out_k(const __half* __restrict__ qkv, const float* __restrict__ mw2,
                           const float* __restrict__ mb2, float* __restrict__ mech,
                           float* __restrict__ out_mech)
{
    int row  = blockIdx.x * 8 + (threadIdx.x >> 5);
    int lane = threadIdx.x & 31;
    const __half* r = qkv + (size_t)row * NQKV + 3072;
    float s = 0.f;
#pragma unroll
    for (int c = lane; c < 512; c += 32) s = fmaf(__half2float(r[c]), mw2[c], s);
#pragma unroll
    for (int off = 16; off > 0; off >>= 1) s += __shfl_xor_sync(0xffffffffu, s, off);
    if (lane == 0) {
        float t = s + mb2[0];
        float m = 1.f / (1.f + expf(-t));
        mech[row] = m;
        out_mech[row] = m;
    }
}

// ---------------------------------------------------------------------------
// Host launcher
// ---------------------------------------------------------------------------
extern "C" void kernel_launch(void* const* d_in, const int* in_sizes, int n_in,
                              void* d_out, int out_size)
{
    (void)in_sizes; (void)n_in; (void)out_size;
    const float* x_in = (const float*)d_in[0];
    const float* pos  = (const float*)d_in[1];
    const float* tim  = (const float*)d_in[2];
    const float* wi   = (const float*)d_in[3];
    const float* bi   = (const float*)d_in[4];
    const float* g1   = (const float*)d_in[5];
    const float* be1  = (const float*)d_in[6];
    const float* g2   = (const float*)d_in[7];
    const float* be2  = (const float*)d_in[8];
    const float* g3   = (const float*)d_in[9];
    const float* be3  = (const float*)d_in[10];
    const float* qw   = (const float*)d_in[11];
    const float* qb   = (const float*)d_in[12];
    const float* kw   = (const float*)d_in[13];
    const float* kb   = (const float*)d_in[14];
    const float* vw   = (const float*)d_in[15];
    const float* vb   = (const float*)d_in[16];
    const float* ow   = (const float*)d_in[17];
    const float* ob   = (const float*)d_in[18];
    const float* mw1  = (const float*)d_in[19];
    const float* mb1  = (const float*)d_in[20];
    const float* mw2  = (const float*)d_in[21];
    const float* mb2  = (const float*)d_in[22];
    const float* ew   = (const float*)d_in[23];
    const float* eb   = (const float*)d_in[24];
    const float* elw  = (const float*)d_in[25];
    const float* fw1  = (const float*)d_in[26];
    const float* fb1  = (const float*)d_in[27];
    const float* fw2  = (const float*)d_in[28];
    const float* fb2  = (const float*)d_in[29];

    float* out = (float*)d_out;
    float* out_mech = out + NXD;
    float* out_w    = out + NXD + BS;

    float* fb = nullptr;
    cudaGetSymbolAddress((void**)&fb, g_buf);
    float* gx    = fb + OFF_X;
    float* gpep  = fb + OFF_PEP;
    float* gmech = fb + OFF_MECH;
    float* gb5   = fb + OFF_B5;
    float* gwsm  = fb + OFF_WSM;
    float* gbqkv = fb + OFF_BQKV;

    __half *h16, *qkv16, *ctx16, *ffh16, *pe16, *w16;
    cudaGetSymbolAddress((void**)&h16,   g_h16);
    cudaGetSymbolAddress((void**)&qkv16, g_qkv16);
    cudaGetSymbolAddress((void**)&ctx16, g_ctx16);
    cudaGetSymbolAddress((void**)&ffh16, g_ffh16);
    cudaGetSymbolAddress((void**)&pe16,  g_pe16);
    cudaGetSymbolAddress((void**)&w16,   g_w16);

    // weight conversions (fp32 -> fp16)
    cvt8_k<<<(Dc * Dc / 8 + 255) / 256, 256>>>((const float4*)wi,  (uint4*)(w16 + W16_WI),  Dc * Dc / 8);
    cvt8_k<<<(Dc * Dc / 8 + 255) / 256, 256>>>((const float4*)ow,  (uint4*)(w16 + W16_OW),  Dc * Dc / 8);
    cvt8_k<<<(Dc * DFFc / 8 + 255) / 256, 256>>>((const float4*)fw1, (uint4*)(w16 + W16_FW1), Dc * DFFc / 8);
    cvt8_k<<<(DFFc * Dc / 8 + 255) / 256, 256>>>((const float4*)fw2, (uint4*)(w16 + W16_FW2), DFFc * Dc / 8);
    pack_qkvm_k<<<(Dc * 448) / 256, 256>>>(qw, kw, vw, mw1, qb, kb, vb, mb1,
                                           w16 + W16_QKV, gbqkv);

    // 1) positional/timing embedding
    build_pe_k<<<(Sc * Dc / 4) / 256, 256>>>(pos, tim, pe16);
    hgemm_k<<<dim3(Dc / 128, Sc / 256), 512>>>(pe16, w16 + W16_WI, bi, nullptr, gpep,
                                               Sc, Dc, Dc, 0, 0);
    // 2) x = x_in + pep; norm1 -> h16  (fused)
    ln_addpe_k<<<BS, 256>>>(x_in, gpep, g1, be1, gx, h16);

    // 3) fused QKV + mech-hidden projection (fp16 out)
    hgemm_k<<<dim3(NQKV / 128, BS / 256), 512>>>(h16, w16 + W16_QKV, gbqkv, nullptr, qkv16,
                                                 BS, NQKV, Dc, 2, 1);

    // 4) mechanism output
    mech_out_k<<<BS / 8, 256>>>(qkv16, mw2, mb2, gmech, out_mech);

    // 5) fp16 flash attention -> ctx16
    attn_h_k<<<dim3(Sc / 128, Bc * Hc), 256>>>(qkv16, gmech, ctx16);

    // 6) output projection + residual
    hgemm_k<<<dim3(Dc / 128, BS / 256), 512>>>(ctx16, w16 + W16_OW, ob, gx, gx,
                                               BS, Dc, Dc, 0, 0);

    // 7) five elements (folded to one GEMM)
    layernorm_k<<<BS, 256>>>(gx, g2, be2, h16);
    softmax5_k<<<1, 32>>>(elw, gwsm, out_w);
    combine_w5_k<<<(Dc * Dc / 4) / 256, 256>>>(ew, gwsm, w16 + W16_W5);
    combine_b5_k<<<Dc / 256, 256>>>(eb, gwsm, gb5);
    hgemm_k<<<dim3(Dc / 128, BS / 256), 512>>>(h16, w16 + W16_W5, gb5, gx, gx,
                                               BS, Dc, Dc, 0, 0);

    // 8) FFN
    layernorm_k<<<BS, 256>>>(gx, g3, be3, h16);
    hgemm_k<<<dim3(DFFc / 128, BS / 256), 512>>>(h16, w16 + W16_FW1, fb1, nullptr, ffh16,
                                                 BS, DFFc, Dc, 1, 1);
    hgemm_k<<<dim3(Dc / 128, BS / 256), 512>>>(ffh16, w16 + W16_FW2, fb2, gx, out,
                                               BS, Dc, DFFc, 0, 0);
}

// round 12
// speedup vs baseline: 1.1683x; 1.1683x over previous
#include <cuda_runtime.h>
#include <cuda_fp16.h>
#include <math.h>
#include <stdint.h>

// ---------------------------------------------------------------------------
// MechanismTransformerBlock  B=8 S=1024 D=1024 H=16 DH=64 DFF=4096
// fp16 tensor-core path (R8 structure: 128x128 tile, 256 thr, 2 CTAs/SM):
//  - hgemm: BK=32 (two R8 subtiles per stage), 3-stage cp.async ring
//  - attention: double-buffered cp.async K/V, mech factor applied post-MMA
// ---------------------------------------------------------------------------

namespace {
constexpr int Bc = 8, Sc = 1024, Dc = 1024, Hc = 16, DFFc = 4096;
constexpr int BS = Bc * Sc;                       // 8192 rows
constexpr size_t NXD = (size_t)BS * Dc;           // 8,388,608
constexpr int NQKV = 3584;                        // q|k|v|mech-hidden

// fp32 scratch
constexpr size_t OFF_X    = 0;
constexpr size_t OFF_PEP  = OFF_X   + NXD;                    // S x D
constexpr size_t OFF_MECH = OFF_PEP + (size_t)Sc * Dc;        // BS
constexpr size_t OFF_B5   = OFF_MECH+ (size_t)BS;             // D
constexpr size_t OFF_WSM  = OFF_B5  + Dc;                     // 8
constexpr size_t OFF_BQKV = OFF_WSM + 8;                      // 3584
constexpr size_t TOTALF   = OFF_BQKV + NQKV;

// fp16 weight staging offsets (in halfs)
constexpr size_t W16_WI  = 0;
constexpr size_t W16_OW  = W16_WI  + (size_t)Dc * Dc;
constexpr size_t W16_W5  = W16_OW  + (size_t)Dc * Dc;
constexpr size_t W16_FW1 = W16_W5  + (size_t)Dc * Dc;
constexpr size_t W16_FW2 = W16_FW1 + (size_t)Dc * DFFc;
constexpr size_t W16_QKV = W16_FW2 + (size_t)DFFc * Dc;
constexpr size_t W16_TOT = W16_QKV + (size_t)Dc * NQKV;
}

__device__ float  g_buf[TOTALF];
__device__ __half g_h16[NXD];                 // LN output
__device__ __half g_qkv16[(size_t)BS * NQKV]; // q|k|v|mech-hidden
__device__ __half g_ctx16[NXD];               // attention output
__device__ __half g_ffh16[(size_t)BS * DFFc]; // FFN hidden
__device__ __half g_pe16[(size_t)Sc * Dc];
__device__ __half g_w16[W16_TOT];

__device__ __forceinline__ float gelu_exact(float v) {
    return 0.5f * v * (1.0f + erff(v * 0.70710678118654752440f));
}

__device__ __forceinline__ void mma_f16(float* c, const uint32_t* a, uint32_t b0, uint32_t b1) {
    asm volatile(
        "mma.sync.aligned.m16n8k16.row.col.f32.f16.f16.f32 "
        "{%0,%1,%2,%3}, {%4,%5,%6,%7}, {%8,%9}, {%0,%1,%2,%3};\n"
        : "+f"(c[0]), "+f"(c[1]), "+f"(c[2]), "+f"(c[3])
        : "r"(a[0]), "r"(a[1]), "r"(a[2]), "r"(a[3]), "r"(b0), "r"(b1));
}

__device__ __forceinline__ void ldsm_x4(uint32_t& r0, uint32_t& r1, uint32_t& r2, uint32_t& r3,
                                        uint32_t addr) {
    asm volatile("ldmatrix.sync.aligned.m8n8.x4.shared.b16 {%0,%1,%2,%3}, [%4];"
                 : "=r"(r0), "=r"(r1), "=r"(r2), "=r"(r3) : "r"(addr));
}

__device__ __forceinline__ void ldsm_x4t(uint32_t& r0, uint32_t& r1, uint32_t& r2, uint32_t& r3,
                                         uint32_t addr) {
    asm volatile("ldmatrix.sync.aligned.m8n8.x4.trans.shared.b16 {%0,%1,%2,%3}, [%4];"
                 : "=r"(r0), "=r"(r1), "=r"(r2), "=r"(r3) : "r"(addr));
}

__device__ __forceinline__ uint32_t h2bits(float lo, float hi) {
    __half2 h = __floats2half2_rn(lo, hi);
    return *reinterpret_cast<uint32_t*>(&h);
}

__device__ __forceinline__ void cp16(uint32_t smem, const void* g) {
    asm volatile("cp.async.cg.shared.global [%0], [%1], 16;" :: "r"(smem), "l"(g));
}
__device__ __forceinline__ void cp_commit() {
    asm volatile("cp.async.commit_group;");
}
template <int N>
__device__ __forceinline__ void cp_wait() {
    asm volatile("cp.async.wait_group %0;" :: "n"(N));
}

// ---------------------------------------------------------------------------
// fp16 GEMM, 3-stage cp.async pipeline, BK=32.
// 128x128 tile, 256 thr = 8 warps (4M x 2N), warp tile 32x64.
// Each stage = 16KB: A subtiles k0-15 / k16-31 (4KB each, R8 layout
// [m][16] swz c^((m>>2)&1)), B subtiles (4KB each, [k][128] swz c^(k&7)).
// A ring 0..24KB, B ring 24..48KB.  Static smem 48KB -> 2 CTAs/SM.
// act: 0 none, 1 gelu, 2 gelu iff global col >= 3072.  K % 32 == 0.
// ---------------------------------------------------------------------------
__global__ void __launch_bounds__(256, 2)
hgemm_k(const __half* __restrict__ A, const __half* __restrict__ Bm,
        const float* __restrict__ bias, const float* __restrict__ resid,
        void* __restrict__ Cv, int M, int N, int K, int act, int outh)
{
    __shared__ __align__(16) unsigned char smem[49152];
    const uint32_t smem_base = (uint32_t)__cvta_generic_to_shared(smem);

    const int tid = threadIdx.x;
    const int w = tid >> 5, l = tid & 31;
    const int wm = (w & 3) * 32;
    const int wn = (w >> 2) * 64;
    const int g = l >> 2, t = l & 3;
    const int bn = blockIdx.x, bm = blockIdx.y;
    const __half* Ab = A + (size_t)bm * 128 * K;
    const __half* Bb = Bm + (size_t)bn * 128;

    const int arow = tid >> 1;            // 0..127
    const int ac   = tid & 1;
    const int brow = tid >> 4;            // 0..15
    const int bc   = tid & 15;

    const uint32_t a_st = smem_base + arow * 32 + ((ac ^ ((arow >> 2) & 1)) << 4);
    const uint32_t b_st = smem_base + 24576 + brow * 256 + ((bc ^ (brow & 7)) << 4);
    const __half* a_gp = Ab + (size_t)arow * K + ac * 8;
    const __half* b_gp = Bb + (size_t)brow * N + bc * 8;

    const int amr = ((l >> 3) & 1) * 8 + (l & 7);
    const int acf = l >> 4;
    const int bkk = ((l >> 4) & 1) * 8 + (l & 7);
    const int bcb = (wn >> 3) + ((l >> 3) & 1);

    const int NIT = K >> 5;

    float acc[2][8][4];
#pragma unroll
    for (int i = 0; i < 2; i++)
#pragma unroll
        for (int j = 0; j < 8; j++)
#pragma unroll
            for (int r = 0; r < 4; r++) acc[i][j][r] = 0.f;

    // prologue: stages 0,1 (each = k tile of 32)
#pragma unroll
    for (int s = 0; s < 2; s++) {
        cp16(a_st + s * 8192,        a_gp + s * 32);
        cp16(a_st + s * 8192 + 4096, a_gp + s * 32 + 16);
        cp16(b_st + s * 8192,        b_gp + (size_t)(s * 32) * N);
        cp16(b_st + s * 8192 + 4096, b_gp + (size_t)(s * 32 + 16) * N);
        cp_commit();
    }

    int st = 0;
    for (int it = 0; it < NIT; it++) {
        cp_wait<1>();            // stage it arrived
        __syncthreads();         // stage (it+2)%3 provably drained
        {
            int nx = it + 2;
            if (nx < NIT) {
                int ring = nx - (nx / 3) * 3;
                cp16(a_st + ring * 8192,        a_gp + nx * 32);
                cp16(a_st + ring * 8192 + 4096, a_gp + nx * 32 + 16);
                cp16(b_st + ring * 8192,        b_gp + (size_t)(nx * 32) * N);
                cp16(b_st + ring * 8192 + 4096, b_gp + (size_t)(nx * 32 + 16) * N);
            }
            cp_commit();
        }
#pragma unroll
        for (int ks = 0; ks < 2; ks++) {
            const uint32_t abuf = smem_base + st * 8192 + ks * 4096;
            const uint32_t bbuf = smem_base + 24576 + st * 8192 + ks * 4096;
            uint32_t af[2][4];
#pragma unroll
            for (int i = 0; i < 2; i++) {
                int m = wm + i * 16 + amr;
                uint32_t ad = abuf + m * 32 + ((acf ^ ((m >> 2) & 1)) << 4);
                ldsm_x4(af[i][0], af[i][1], af[i][2], af[i][3], ad);
            }
#pragma unroll
            for (int jp = 0; jp < 4; jp++) {
                int cB = bcb + jp * 2;
                uint32_t bd = bbuf + bkk * 256 + ((cB ^ (bkk & 7)) << 4);
                uint32_t r0, r1, r2, r3;
                ldsm_x4t(r0, r1, r2, r3, bd);
#pragma unroll
                for (int i = 0; i < 2; i++) {
                    mma_f16(acc[i][jp * 2],     af[i], r0, r2);
                    mma_f16(acc[i][jp * 2 + 1], af[i], r1, r3);
                }
            }
        }
        st++; if (st == 3) st = 0;
    }

#pragma unroll
    for (int i = 0; i < 2; i++) {
        int row0 = bm * 128 + wm + i * 16 + g;
        int row1 = row0 + 8;
        size_t ro0 = (size_t)row0 * N;
        size_t ro1 = (size_t)row1 * N;
#pragma unroll
        for (int j = 0; j < 8; j++) {
            int col = bn * 128 + wn + j * 8 + 2 * t;
            float v0 = acc[i][j][0], v1 = acc[i][j][1];
            float v2 = acc[i][j][2], v3 = acc[i][j][3];
            if (bias) {
                float b0 = bias[col], b1 = bias[col + 1];
                v0 += b0; v1 += b1; v2 += b0; v3 += b1;
            }
            bool dg = (act == 1) || (act == 2 && col >= 3072);
            if (dg) {
                v0 = gelu_exact(v0); v1 = gelu_exact(v1);
                v2 = gelu_exact(v2); v3 = gelu_exact(v3);
            }
            if (resid) {
                v0 += resid[ro0 + col]; v1 += resid[ro0 + col + 1];
                v2 += resid[ro1 + col]; v3 += resid[ro1 + col + 1];
            }
            if (outh) {
                __half* C = (__half*)Cv;
                *(uint32_t*)&C[ro0 + col] = h2bits(v0, v1);
                *(uint32_t*)&C[ro1 + col] = h2bits(v2, v3);
            } else {
                float* C = (float*)Cv;
                *(float2*)&C[ro0 + col] = make_float2(v0, v1);
                *(float2*)&C[ro1 + col] = make_float2(v2, v3);
            }
        }
    }
}

// ---------------------------------------------------------------------------
// fp16 flash attention with double-buffered cp.async K/V.
// QKV fp16 [BS][3584].  Mech factor (0.125*(1+mech)) applied to score
// fragments post-MMA in fp32 (key = j*8 + 2t from fragment layout).
// smem: Q 16KB | K 2x8KB | V 2x8KB | fac 2x64 fl  = 49664 B (dynamic).
// ---------------------------------------------------------------------------
__device__ __forceinline__ uint32_t aswz(int r, int c) {
    return (uint32_t)(r * 128 + ((c ^ ((r + (r >> 3)) & 7)) << 4));
}

__global__ void __launch_bounds__(256)
attn_h_k(const __half* __restrict__ QKV, const float* __restrict__ mech,
         __half* __restrict__ Octx)
{
    extern __shared__ __align__(16) unsigned char asmem[];
    const uint32_t sb = (uint32_t)__cvta_generic_to_shared(asmem);
    const uint32_t kb = sb + 16384;
    const uint32_t vb = sb + 32768;
    float* facs = (float*)(asmem + 49152);   // [2][64]

    const int tid = threadIdx.x;
    const int w = tid >> 5, l = tid & 31;
    const int g = l >> 2, t = l & 3;
    const int bh = blockIdx.y;
    const int b = bh >> 4, h = bh & 15;
    const int q0 = blockIdx.x * 128;
    const int qr = w * 16;

    // ---- load Q tile (plain loads) ----
    {
        int r = tid >> 1;
        int c0 = (tid & 1) * 4;
        const __half* qp = QKV + ((size_t)(b * 1024 + q0 + r)) * NQKV + h * 64;
#pragma unroll
        for (int u = 0; u < 4; u++) {
            int c = c0 + u;
            uint4 v = *(const uint4*)(qp + c * 8);
            asm volatile("st.shared.v4.u32 [%0], {%1,%2,%3,%4};" ::
                         "r"(sb + aswz(r, c)), "r"(v.x), "r"(v.y), "r"(v.z), "r"(v.w));
        }
    }

    // ---- prologue: cp.async K/V tile 0, prefetch mech ----
    const int kvr = tid >> 2;
    const int kvc0 = (tid & 3) * 2;
    {
        size_t rowb = ((size_t)(b * 1024 + kvr)) * NQKV + h * 64;
#pragma unroll
        for (int u = 0; u < 2; u++) {
            int c = kvc0 + u;
            cp16(kb + aswz(kvr, c), QKV + rowb + 1024 + c * 8);
            cp16(vb + aswz(kvr, c), QKV + rowb + 2048 + c * 8);
        }
        cp_commit();
    }
    float facr = 0.f;
    if (tid < 64) facr = mech[(size_t)b * 1024 + tid];

    float m0 = -1e30f, m1 = -1e30f, l0 = 0.f, l1 = 0.f;
    float acc[8][4];
#pragma unroll
    for (int e = 0; e < 8; e++)
#pragma unroll
        for (int r = 0; r < 4; r++) acc[e][r] = 0.f;
    __syncthreads();   // Q visible

    for (int kt = 0; kt < 16; kt++) {
        cp_wait<0>();                       // K/V tile kt arrived
        if (tid < 64) facs[(kt & 1) * 64 + tid] = 0.125f * (1.f + facr);
        __syncthreads();                    // K/V + fac visible; old buffer free

        if (kt + 1 < 16) {
            const int nb = (kt + 1) & 1;
            size_t rowb = ((size_t)(b * 1024 + (kt + 1) * 64 + kvr)) * NQKV + h * 64;
#pragma unroll
            for (int u = 0; u < 2; u++) {
                int c = kvc0 + u;
                cp16(kb + nb * 8192 + aswz(kvr, c), QKV + rowb + 1024 + c * 8);
                cp16(vb + nb * 8192 + aswz(kvr, c), QKV + rowb + 2048 + c * 8);
            }
            cp_commit();
            if (tid < 64) facr = mech[(size_t)b * 1024 + (kt + 1) * 64 + tid];
        }

        const uint32_t kbuf = kb + (kt & 1) * 8192;
        const uint32_t vbuf = vb + (kt & 1) * 8192;
        const float* fac = facs + (kt & 1) * 64;

        // ---- S = Q K^T ----
        float s[8][4];
#pragma unroll
        for (int j = 0; j < 8; j++)
#pragma unroll
            for (int r = 0; r < 4; r++) s[j][r] = 0.f;
#pragma unroll
        for (int kc = 0; kc < 4; kc++) {
            uint32_t a[4];
            {
                int row = qr + (l & 7) + ((l >> 3) & 1) * 8;
                int chunk = 2 * kc + (l >> 4);
                ldsm_x4(a[0], a[1], a[2], a[3], sb + aswz(row, chunk));
            }
#pragma unroll
            for (int jp = 0; jp < 4; jp++) {
                int key = jp * 16 + ((l >> 4) & 1) * 8 + (l & 7);
                int chunk = 2 * kc + ((l >> 3) & 1);
                uint32_t r0, r1, r2, r3;
                ldsm_x4(r0, r1, r2, r3, kbuf + aswz(key, chunk));
                mma_f16(s[jp * 2],     a, r0, r1);
                mma_f16(s[jp * 2 + 1], a, r2, r3);
            }
        }

        // ---- apply mech factor (per-key, fp32) ----
#pragma unroll
        for (int j = 0; j < 8; j++) {
            float2 f = *(const float2*)&fac[j * 8 + 2 * t];
            s[j][0] *= f.x; s[j][1] *= f.y;
            s[j][2] *= f.x; s[j][3] *= f.y;
        }

        // ---- online softmax ----
        float mx0 = -1e30f, mx1 = -1e30f;
#pragma unroll
        for (int j = 0; j < 8; j++) {
            mx0 = fmaxf(mx0, fmaxf(s[j][0], s[j][1]));
            mx1 = fmaxf(mx1, fmaxf(s[j][2], s[j][3]));
        }
        mx0 = fmaxf(mx0, __shfl_xor_sync(0xffffffffu, mx0, 1));
        mx0 = fmaxf(mx0, __shfl_xor_sync(0xffffffffu, mx0, 2));
        mx1 = fmaxf(mx1, __shfl_xor_sync(0xffffffffu, mx1, 1));
        mx1 = fmaxf(mx1, __shfl_xor_sync(0xffffffffu, mx1, 2));
        float mn0 = fmaxf(m0, mx0), mn1 = fmaxf(m1, mx1);
        float al0 = __expf(m0 - mn0), al1 = __expf(m1 - mn1);
        float sum0 = 0.f, sum1 = 0.f;
#pragma unroll
        for (int j = 0; j < 8; j++) {
            s[j][0] = __expf(s[j][0] - mn0);
            s[j][1] = __expf(s[j][1] - mn0);
            s[j][2] = __expf(s[j][2] - mn1);
            s[j][3] = __expf(s[j][3] - mn1);
            sum0 += s[j][0] + s[j][1];
            sum1 += s[j][2] + s[j][3];
        }
        sum0 += __shfl_xor_sync(0xffffffffu, sum0, 1);
        sum0 += __shfl_xor_sync(0xffffffffu, sum0, 2);
        sum1 += __shfl_xor_sync(0xffffffffu, sum1, 1);
        sum1 += __shfl_xor_sync(0xffffffffu, sum1, 2);
        l0 = l0 * al0 + sum0;
        l1 = l1 * al1 + sum1;
        m0 = mn0; m1 = mn1;
#pragma unroll
        for (int e = 0; e < 8; e++) {
            acc[e][0] *= al0; acc[e][1] *= al0;
            acc[e][2] *= al1; acc[e][3] *= al1;
        }

        // ---- acc += P V ----
#pragma unroll
        for (int u = 0; u < 4; u++) {
            uint32_t a[4];
            a[0] = h2bits(s[2 * u][0],     s[2 * u][1]);
            a[1] = h2bits(s[2 * u][2],     s[2 * u][3]);
            a[2] = h2bits(s[2 * u + 1][0], s[2 * u + 1][1]);
            a[3] = h2bits(s[2 * u + 1][2], s[2 * u + 1][3]);
#pragma unroll
            for (int ep = 0; ep < 4; ep++) {
                int key = u * 16 + ((l >> 3) & 1) * 8 + (l & 7);
                int chunk = ep * 2 + (l >> 4);
                uint32_t r0, r1, r2, r3;
                ldsm_x4t(r0, r1, r2, r3, vbuf + aswz(key, chunk));
                mma_f16(acc[ep * 2],     a, r0, r1);
                mma_f16(acc[ep * 2 + 1], a, r2, r3);
            }
        }
    }

    float inv0 = 1.f / l0, inv1 = 1.f / l1;
    size_t o0 = ((size_t)(b * 1024 + q0 + qr + g)) * 1024 + h * 64;
    size_t o1 = o0 + (size_t)8 * 1024;
#pragma unroll
    for (int e = 0; e < 8; e++) {
        *(uint32_t*)&Octx[o0 + e * 8 + 2 * t] = h2bits(acc[e][0] * inv0, acc[e][1] * inv0);
        *(uint32_t*)&Octx[o1 + e * 8 + 2 * t] = h2bits(acc[e][2] * inv1, acc[e][3] * inv1);
    }
}

// ---------------------------------------------------------------------------
// LayerNorm (1024) -> fp16. One block per row.
// ---------------------------------------------------------------------------
__global__ void layernorm_k(const float* __restrict__ x, const float* __restrict__ g,
                            const float* __restrict__ b, __half* __restrict__ o)
{
    int row = blockIdx.x;
    const float4* xr = (const float4*)(x + (size_t)row * 1024);
    float4 v = xr[threadIdx.x];
    float s  = v.x + v.y + v.z + v.w;
    float ss = fmaf(v.x, v.x, fmaf(v.y, v.y, fmaf(v.z, v.z, v.w * v.w)));
#pragma unroll
    for (int off = 16; off > 0; off >>= 1) {
        s  += __shfl_xor_sync(0xffffffffu, s,  off);
        ss += __shfl_xor_sync(0xffffffffu, ss, off);
    }
    __shared__ float ws[8], wss[8];
    __shared__ float s_mean, s_inv;
    int w = threadIdx.x >> 5, ln = threadIdx.x & 31;
    if (ln == 0) { ws[w] = s; wss[w] = ss; }
    __syncthreads();
    if (threadIdx.x == 0) {
        float S = 0.f, SS = 0.f;
#pragma unroll
        for (int i = 0; i < 8; i++) { S += ws[i]; SS += wss[i]; }
        float mean = S * (1.f / 1024.f);
        float var  = SS * (1.f / 1024.f) - mean * mean;
        s_mean = mean;
        s_inv  = rsqrtf(var + 1e-5f);
    }
    __syncthreads();
    float mean = s_mean, inv = s_inv;
    float4 gv = ((const float4*)g)[threadIdx.x];
    float4 bv = ((const float4*)b)[threadIdx.x];
    uint2 r;
    r.x = h2bits((v.x - mean) * inv * gv.x + bv.x, (v.y - mean) * inv * gv.y + bv.y);
    r.y = h2bits((v.z - mean) * inv * gv.z + bv.z, (v.w - mean) * inv * gv.w + bv.w);
    *(uint2*)&o[(size_t)row * 1024 + threadIdx.x * 4] = r;
}

// Fused: x = x_in + pep (write fp32 residual) AND layernorm(x) -> fp16.
__global__ void ln_addpe_k(const float* __restrict__ xin, const float* __restrict__ pep,
                           const float* __restrict__ g, const float* __restrict__ b,
                           float* __restrict__ xo, __half* __restrict__ o)
{
    int row = blockIdx.x;
    float4 xi = ((const float4*)(xin + (size_t)row * 1024))[threadIdx.x];
    float4 pe = ((const float4*)(pep + (size_t)(row & 1023) * 1024))[threadIdx.x];
    float4 v = make_float4(xi.x + pe.x, xi.y + pe.y, xi.z + pe.z, xi.w + pe.w);
    ((float4*)(xo + (size_t)row * 1024))[threadIdx.x] = v;
    float s  = v.x + v.y + v.z + v.w;
    float ss = fmaf(v.x, v.x, fmaf(v.y, v.y, fmaf(v.z, v.z, v.w * v.w)));
#pragma unroll
    for (int off = 16; off > 0; off >>= 1) {
        s  += __shfl_xor_sync(0xffffffffu, s,  off);
        ss += __shfl_xor_sync(0xffffffffu, ss, off);
    }
    __shared__ float ws[8], wss[8];
    __shared__ float s_mean, s_inv;
    int w = threadIdx.x >> 5, ln = threadIdx.x & 31;
    if (ln == 0) { ws[w] = s; wss[w] = ss; }
    __syncthreads();
    if (threadIdx.x == 0) {
        float S = 0.f, SS = 0.f;
#pragma unroll
        for (int i = 0; i < 8; i++) { S += ws[i]; SS += wss[i]; }
        float mean = S * (1.f / 1024.f);
        float var  = SS * (1.f / 1024.f) - mean * mean;
        s_mean = mean;
        s_inv  = rsqrtf(var + 1e-5f);
    }
    __syncthreads();
    float mean = s_mean, inv = s_inv;
    float4 gv = ((const float4*)g)[threadIdx.x];
    float4 bv = ((const float4*)b)[threadIdx.x];
    uint2 r;
    r.x = h2bits((v.x - mean) * inv * gv.x + bv.x, (v.y - mean) * inv * gv.y + bv.y);
    r.y = h2bits((v.z - mean) * inv * gv.z + bv.z, (v.w - mean) * inv * gv.w + bv.w);
    *(uint2*)&o[(size_t)row * 1024 + threadIdx.x * 4] = r;
}

// ---------------------------------------------------------------------------
// Prep kernels (vectorized)
// ---------------------------------------------------------------------------
__global__ void cvt8_k(const float4* __restrict__ src, uint4* __restrict__ dst, int n8)
{
    int i = blockIdx.x * blockDim.x + threadIdx.x;
    if (i >= n8) return;
    float4 a = src[2 * i], b = src[2 * i + 1];
    dst[i] = make_uint4(h2bits(a.x, a.y), h2bits(a.z, a.w),
                        h2bits(b.x, b.y), h2bits(b.z, b.w));
}

__global__ void build_pe_k(const float* __restrict__ pos, const float* __restrict__ tim,
                           __half* __restrict__ pe)
{
    int i = (blockIdx.x * blockDim.x + threadIdx.x) * 4;   // S*D
    int s = i >> 10, d = i & 1023;
    const float* srcp = (d < 512) ? pos + s * 512 + d : tim + s * 512 + (d - 512);
    float4 v = *(const float4*)srcp;
    *(uint2*)&pe[i] = make_uint2(h2bits(v.x, v.y), h2bits(v.z, v.w));
}

__global__ void softmax5_k(const float* __restrict__ elw, float* __restrict__ wsm,
                           float* __restrict__ out_w)
{
    if (threadIdx.x == 0) {
        float m = elw[0];
        for (int p = 1; p < 5; p++) m = fmaxf(m, elw[p]);
        float e[5], s = 0.f;
        for (int p = 0; p < 5; p++) { e[p] = expf(elw[p] - m); s += e[p]; }
        float inv = 1.f / s;
        for (int p = 0; p < 5; p++) { wsm[p] = e[p] * inv; out_w[p] = e[p] * inv; }
    }
}

__global__ void combine_w5_k(const float* __restrict__ ew, const float* __restrict__ wsm,
                             __half* __restrict__ w5)
{
    int i = (blockIdx.x * blockDim.x + threadIdx.x) * 4;   // D*D
    float w0 = wsm[0], w1 = wsm[1], w2 = wsm[2], w3 = wsm[3], w4 = wsm[4];
    const size_t DD = (size_t)1024 * 1024;
    float4 e0 = *(const float4*)&ew[i];
    float4 e1 = *(const float4*)&ew[DD + i];
    float4 e2 = *(const float4*)&ew[2 * DD + i];
    float4 e3 = *(const float4*)&ew[3 * DD + i];
    float4 e4 = *(const float4*)&ew[4 * DD + i];
    float vx = w0 * e0.x + w1 * e1.x + w2 * e2.x + w3 * e3.x + w4 * e4.x;
    float vy = w0 * e0.y + w1 * e1.y + w2 * e2.y + w3 * e3.y + w4 * e4.y;
    float vz = w0 * e0.z + w1 * e1.z + w2 * e2.z + w3 * e3.z + w4 * e4.z;
    float vw = w0 * e0.w + w1 * e1.w + w2 * e2.w + w3 * e3.w + w4 * e4.w;
    *(uint2*)&w5[i] = make_uint2(h2bits(vx, vy), h2bits(vz, vw));
}

__global__ void combine_b5_k(const float* __restrict__ eb, const float* __restrict__ wsm,
                             float* __restrict__ b5)
{
    int i = blockIdx.x * blockDim.x + threadIdx.x;   // D
    float v = 0.f;
    for (int p = 0; p < 5; p++) v += wsm[p] * eb[p * 1024 + i];
    b5[i] = v;
}

// Pack qw|kw|vw|mw1 -> fp16 [D][3584]; biases -> fp32 [3584]. 8 cols/thread.
__global__ void pack_qkvm_k(const float* __restrict__ qw, const float* __restrict__ kw,
                            const float* __restrict__ vw, const float* __restrict__ mw1,
                            const float* __restrict__ qb, const float* __restrict__ kb,
                            const float* __restrict__ vb, const float* __restrict__ mb1,
                            __half* __restrict__ wq, float* __restrict__ bq)
{
    int i = blockIdx.x * blockDim.x + threadIdx.x;   // D * 448
    int k = i / 448, n = (i - k * 448) * 8;
    const float* sp;
    if (n < 1024)      sp = qw  + k * 1024 + n;
    else if (n < 2048) sp = kw  + k * 1024 + (n - 1024);
    else if (n < 3072) sp = vw  + k * 1024 + (n - 2048);
    else               sp = mw1 + k * 512  + (n - 3072);
    float4 a = *(const float4*)sp;
    float4 b = *(const float4*)(sp + 4);
    *(uint4*)&wq[(size_t)k * NQKV + n] =
        make_uint4(h2bits(a.x, a.y), h2bits(a.z, a.w), h2bits(b.x, b.y), h2bits(b.z, b.w));
    if (i < NQKV) {
        float bb;
        if (i < 1024)      bb = qb[i];
        else if (i < 2048) bb = kb[i - 1024];
        else if (i < 3072) bb = vb[i - 2048];
        else               bb = mb1[i - 3072];
        bq[i] = bb;
    }
}

// mech[r] = sigmoid(dot(qkv16[r, 3072:3584], mw2) + mb2); one warp per row.
__global__ void mech_out_k(const __half* __restrict__ qkv, const float* __restrict__ mw2,
                           const float* __restrict__ mb2, float* __restrict__ mech,
                           float* __restrict__ out_mech)
{
    int row  = blockIdx.x * 8 + (threadIdx.x >> 5);
    int lane = threadIdx.x & 31;
    const __half* r = qkv + (size_t)row * NQKV + 3072;
    float s = 0.f;
#pragma unroll
    for (int c = lane; c < 512; c += 32) s = fmaf(__half2float(r[c]), mw2[c], s);
#pragma unroll
    for (int off = 16; off > 0; off >>= 1) s += __shfl_xor_sync(0xffffffffu, s, off);
    if (lane == 0) {
        float t = s + mb2[0];
        float m = 1.f / (1.f + expf(-t));
        mech[row] = m;
        out_mech[row] = m;
    }
}

// ---------------------------------------------------------------------------
// Host launcher
// ---------------------------------------------------------------------------
extern "C" void kernel_launch(void* const* d_in, const int* in_sizes, int n_in,
                              void* d_out, int out_size)
{
    (void)in_sizes; (void)n_in; (void)out_size;
    const float* x_in = (const float*)d_in[0];
    const float* pos  = (const float*)d_in[1];
    const float* tim  = (const float*)d_in[2];
    const float* wi   = (const float*)d_in[3];
    const float* bi   = (const float*)d_in[4];
    const float* g1   = (const float*)d_in[5];
    const float* be1  = (const float*)d_in[6];
    const float* g2   = (const float*)d_in[7];
    const float* be2  = (const float*)d_in[8];
    const float* g3   = (const float*)d_in[9];
    const float* be3  = (const float*)d_in[10];
    const float* qw   = (const float*)d_in[11];
    const float* qb   = (const float*)d_in[12];
    const float* kw   = (const float*)d_in[13];
    const float* kb   = (const float*)d_in[14];
    const float* vw   = (const float*)d_in[15];
    const float* vb   = (const float*)d_in[16];
    const float* ow   = (const float*)d_in[17];
    const float* ob   = (const float*)d_in[18];
    const float* mw1  = (const float*)d_in[19];
    const float* mb1  = (const float*)d_in[20];
    const float* mw2  = (const float*)d_in[21];
    const float* mb2  = (const float*)d_in[22];
    const float* ew   = (const float*)d_in[23];
    const float* eb   = (const float*)d_in[24];
    const float* elw  = (const float*)d_in[25];
    const float* fw1  = (const float*)d_in[26];
    const float* fb1  = (const float*)d_in[27];
    const float* fw2  = (const float*)d_in[28];
    const float* fb2  = (const float*)d_in[29];

    float* out = (float*)d_out;
    float* out_mech = out + NXD;
    float* out_w    = out + NXD + BS;

    float* fb = nullptr;
    cudaGetSymbolAddress((void**)&fb, g_buf);
    float* gx    = fb + OFF_X;
    float* gpep  = fb + OFF_PEP;
    float* gmech = fb + OFF_MECH;
    float* gb5   = fb + OFF_B5;
    float* gwsm  = fb + OFF_WSM;
    float* gbqkv = fb + OFF_BQKV;

    __half *h16, *qkv16, *ctx16, *ffh16, *pe16, *w16;
    cudaGetSymbolAddress((void**)&h16,   g_h16);
    cudaGetSymbolAddress((void**)&qkv16, g_qkv16);
    cudaGetSymbolAddress((void**)&ctx16, g_ctx16);
    cudaGetSymbolAddress((void**)&ffh16, g_ffh16);
    cudaGetSymbolAddress((void**)&pe16,  g_pe16);
    cudaGetSymbolAddress((void**)&w16,   g_w16);

    const int ATTN_SMEM = 49664;
    cudaFuncSetAttribute(attn_h_k, cudaFuncAttributeMaxDynamicSharedMemorySize, ATTN_SMEM);

    // weight conversions (fp32 -> fp16)
    cvt8_k<<<(Dc * Dc / 8 + 255) / 256, 256>>>((const float4*)wi,  (uint4*)(w16 + W16_WI),  Dc * Dc / 8);
    cvt8_k<<<(Dc * Dc / 8 + 255) / 256, 256>>>((const float4*)ow,  (uint4*)(w16 + W16_OW),  Dc * Dc / 8);
    cvt8_k<<<(Dc * DFFc / 8 + 255) / 256, 256>>>((const float4*)fw1, (uint4*)(w16 + W16_FW1), Dc * DFFc / 8);
    cvt8_k<<<(DFFc * Dc / 8 + 255) / 256, 256>>>((const float4*)fw2, (uint4*)(w16 + W16_FW2), DFFc * Dc / 8);
    pack_qkvm_k<<<(Dc * 448) / 256, 256>>>(qw, kw, vw, mw1, qb, kb, vb, mb1,
                                           w16 + W16_QKV, gbqkv);

    // 1) positional/timing embedding
    build_pe_k<<<(Sc * Dc / 4) / 256, 256>>>(pos, tim, pe16);
    hgemm_k<<<dim3(Dc / 128, Sc / 128), 256>>>(pe16, w16 + W16_WI, bi, nullptr, gpep,
                                               Sc, Dc, Dc, 0, 0);
    // 2) x = x_in + pep; norm1 -> h16  (fused)
    ln_addpe_k<<<BS, 256>>>(x_in, gpep, g1, be1, gx, h16);

    // 3) fused QKV + mech-hidden projection (fp16 out)
    hgemm_k<<<dim3(NQKV / 128, BS / 128), 256>>>(h16, w16 + W16_QKV, gbqkv, nullptr, qkv16,
                                                 BS, NQKV, Dc, 2, 1);

    // 4) mechanism output
    mech_out_k<<<BS / 8, 256>>>(qkv16, mw2, mb2, gmech, out_mech);

    // 5) fp16 flash attention -> ctx16
    attn_h_k<<<dim3(Sc / 128, Bc * Hc), 256, ATTN_SMEM>>>(qkv16, gmech, ctx16);

    // 6) output projection + residual
    hgemm_k<<<dim3(Dc / 128, BS / 128), 256>>>(ctx16, w16 + W16_OW, ob, gx, gx,
                                               BS, Dc, Dc, 0, 0);

    // 7) five elements (folded to one GEMM)
    layernorm_k<<<BS, 256>>>(gx, g2, be2, h16);
    softmax5_k<<<1, 32>>>(elw, gwsm, out_w);
    combine_w5_k<<<(Dc * Dc / 4) / 256, 256>>>(ew, gwsm, w16 + W16_W5);
    combine_b5_k<<<Dc / 256, 256>>>(eb, gwsm, gb5);
    hgemm_k<<<dim3(Dc / 128, BS / 128), 256>>>(h16, w16 + W16_W5, gb5, gx, gx,
                                               BS, Dc, Dc, 0, 0);

    // 8) FFN
    layernorm_k<<<BS, 256>>>(gx, g3, be3, h16);
    hgemm_k<<<dim3(DFFc / 128, BS / 128), 256>>>(h16, w16 + W16_FW1, fb1, nullptr, ffh16,
                                                 BS, DFFc, Dc, 1, 1);
    hgemm_k<<<dim3(Dc / 128, BS / 128), 256>>>(ffh16, w16 + W16_FW2, fb2, gx, out,
                                               BS, Dc, DFFc, 0, 0);
}

// round 15
// speedup vs baseline: 1.1739x; 1.0048x over previous
#include <cuda_runtime.h>
#include <cuda_fp16.h>
#include <math.h>
#include <stdint.h>

// ---------------------------------------------------------------------------
// MechanismTransformerBlock  B=8 S=1024 D=1024 H=16 DH=64 DFF=4096
// fp16 tensor-core path (128x128 tile, 256 thr, 2 CTAs/SM):
//  - hgemm: BK=64 (four 4KB subtiles/stage), 3-stage cp.async ring (dyn smem)
//  - attention: double-buffered cp.async K/V, mech factor applied post-MMA
// ---------------------------------------------------------------------------

namespace {
constexpr int Bc = 8, Sc = 1024, Dc = 1024, Hc = 16, DFFc = 4096;
constexpr int BS = Bc * Sc;                       // 8192 rows
constexpr size_t NXD = (size_t)BS * Dc;           // 8,388,608
constexpr int NQKV = 3584;                        // q|k|v|mech-hidden

// fp32 scratch
constexpr size_t OFF_X    = 0;
constexpr size_t OFF_PEP  = OFF_X   + NXD;                    // S x D
constexpr size_t OFF_MECH = OFF_PEP + (size_t)Sc * Dc;        // BS
constexpr size_t OFF_B5   = OFF_MECH+ (size_t)BS;             // D
constexpr size_t OFF_WSM  = OFF_B5  + Dc;                     // 8
constexpr size_t OFF_BQKV = OFF_WSM + 8;                      // 3584
constexpr size_t TOTALF   = OFF_BQKV + NQKV;

// fp16 weight staging offsets (in halfs)
constexpr size_t W16_WI  = 0;
constexpr size_t W16_OW  = W16_WI  + (size_t)Dc * Dc;
constexpr size_t W16_W5  = W16_OW  + (size_t)Dc * Dc;
constexpr size_t W16_FW1 = W16_W5  + (size_t)Dc * Dc;
constexpr size_t W16_FW2 = W16_FW1 + (size_t)Dc * DFFc;
constexpr size_t W16_QKV = W16_FW2 + (size_t)DFFc * Dc;
constexpr size_t W16_TOT = W16_QKV + (size_t)Dc * NQKV;
}

__device__ float  g_buf[TOTALF];
__device__ __half g_h16[NXD];                 // LN output
__device__ __half g_qkv16[(size_t)BS * NQKV]; // q|k|v|mech-hidden
__device__ __half g_ctx16[NXD];               // attention output
__device__ __half g_ffh16[(size_t)BS * DFFc]; // FFN hidden
__device__ __half g_pe16[(size_t)Sc * Dc];
__device__ __half g_w16[W16_TOT];

__device__ __forceinline__ float gelu_exact(float v) {
    return 0.5f * v * (1.0f + erff(v * 0.70710678118654752440f));
}

__device__ __forceinline__ void mma_f16(float* c, const uint32_t* a, uint32_t b0, uint32_t b1) {
    asm volatile(
        "mma.sync.aligned.m16n8k16.row.col.f32.f16.f16.f32 "
        "{%0,%1,%2,%3}, {%4,%5,%6,%7}, {%8,%9}, {%0,%1,%2,%3};\n"
        : "+f"(c[0]), "+f"(c[1]), "+f"(c[2]), "+f"(c[3])
        : "r"(a[0]), "r"(a[1]), "r"(a[2]), "r"(a[3]), "r"(b0), "r"(b1));
}

__device__ __forceinline__ void ldsm_x4(uint32_t& r0, uint32_t& r1, uint32_t& r2, uint32_t& r3,
                                        uint32_t addr) {
    asm volatile("ldmatrix.sync.aligned.m8n8.x4.shared.b16 {%0,%1,%2,%3}, [%4];"
                 : "=r"(r0), "=r"(r1), "=r"(r2), "=r"(r3) : "r"(addr));
}

__device__ __forceinline__ void ldsm_x4t(uint32_t& r0, uint32_t& r1, uint32_t& r2, uint32_t& r3,
                                         uint32_t addr) {
    asm volatile("ldmatrix.sync.aligned.m8n8.x4.trans.shared.b16 {%0,%1,%2,%3}, [%4];"
                 : "=r"(r0), "=r"(r1), "=r"(r2), "=r"(r3) : "r"(addr));
}

__device__ __forceinline__ uint32_t h2bits(float lo, float hi) {
    __half2 h = __floats2half2_rn(lo, hi);
    return *reinterpret_cast<uint32_t*>(&h);
}

__device__ __forceinline__ void cp16(uint32_t smem, const void* g) {
    asm volatile("cp.async.cg.shared.global [%0], [%1], 16;" :: "r"(smem), "l"(g));
}
__device__ __forceinline__ void cp_commit() {
    asm volatile("cp.async.commit_group;");
}
template <int N>
__device__ __forceinline__ void cp_wait() {
    asm volatile("cp.async.wait_group %0;" :: "n"(N));
}

// ---------------------------------------------------------------------------
// fp16 GEMM, 3-stage cp.async pipeline, BK=64 (dynamic smem 96KB).
// 128x128 tile, 256 thr = 8 warps (4M x 2N), warp tile 32x64.
// Stage (32KB) = A subtiles ks=0..3 (4KB each, [m][16] swz c^((m>>2)&1))
//              + B subtiles ks=0..3 (4KB each, [k][128] swz c^(k&7)) at +16KB.
// act: 0 none, 1 gelu, 2 gelu iff global col >= 3072.  K % 64 == 0.
// ---------------------------------------------------------------------------
__global__ void __launch_bounds__(256, 2)
hgemm_k(const __half* __restrict__ A, const __half* __restrict__ Bm,
        const float* __restrict__ bias, const float* __restrict__ resid,
        void* __restrict__ Cv, int M, int N, int K, int act, int outh)
{
    extern __shared__ __align__(16) unsigned char hsm[];
    const uint32_t smem_base = (uint32_t)__cvta_generic_to_shared(hsm);

    const int tid = threadIdx.x;
    const int w = tid >> 5, l = tid & 31;
    const int wm = (w & 3) * 32;
    const int wn = (w >> 2) * 64;
    const int g = l >> 2, t = l & 3;
    const int bn = blockIdx.x, bm = blockIdx.y;
    const __half* Ab = A + (size_t)bm * 128 * K;
    const __half* Bb = Bm + (size_t)bn * 128;

    const int arow = tid >> 1;            // 0..127
    const int ac   = tid & 1;
    const int brow = tid >> 4;            // 0..15
    const int bc   = tid & 15;

    const uint32_t a_st = smem_base + arow * 32 + ((ac ^ ((arow >> 2) & 1)) << 4);
    const uint32_t b_st = smem_base + 16384 + brow * 256 + ((bc ^ (brow & 7)) << 4);
    const __half* a_gp = Ab + (size_t)arow * K + ac * 8;
    const __half* b_gp = Bb + (size_t)brow * N + bc * 8;

    const int amr = ((l >> 3) & 1) * 8 + (l & 7);
    const int acf = l >> 4;
    const int bkk = ((l >> 4) & 1) * 8 + (l & 7);
    const int bcb = (wn >> 3) + ((l >> 3) & 1);

    const int NIT = K >> 6;

    float acc[2][8][4];
#pragma unroll
    for (int i = 0; i < 2; i++)
#pragma unroll
        for (int j = 0; j < 8; j++)
#pragma unroll
            for (int r = 0; r < 4; r++) acc[i][j][r] = 0.f;

    // prologue: stages 0,1 (each = k tile of 64)
#pragma unroll
    for (int s = 0; s < 2; s++) {
#pragma unroll
        for (int ks = 0; ks < 4; ks++) {
            cp16(a_st + s * 32768 + ks * 4096, a_gp + s * 64 + ks * 16);
            cp16(b_st + s * 32768 + ks * 4096, b_gp + (size_t)(s * 64 + ks * 16) * N);
        }
        cp_commit();
    }

    int st = 0;
    for (int it = 0; it < NIT; it++) {
        cp_wait<1>();            // stage it arrived
        __syncthreads();         // stage (it+2)%3 provably drained
        {
            int nx = it + 2;
            if (nx < NIT) {
                int ring = nx - (nx / 3) * 3;
#pragma unroll
                for (int ks = 0; ks < 4; ks++) {
                    cp16(a_st + ring * 32768 + ks * 4096, a_gp + nx * 64 + ks * 16);
                    cp16(b_st + ring * 32768 + ks * 4096,
                         b_gp + (size_t)(nx * 64 + ks * 16) * N);
                }
            }
            cp_commit();
        }
#pragma unroll
        for (int ks = 0; ks < 4; ks++) {
            const uint32_t abuf = smem_base + st * 32768 + ks * 4096;
            const uint32_t bbuf = smem_base + 16384 + st * 32768 + ks * 4096;
            uint32_t af[2][4];
#pragma unroll
            for (int i = 0; i < 2; i++) {
                int m = wm + i * 16 + amr;
                uint32_t ad = abuf + m * 32 + ((acf ^ ((m >> 2) & 1)) << 4);
                ldsm_x4(af[i][0], af[i][1], af[i][2], af[i][3], ad);
            }
#pragma unroll
            for (int jp = 0; jp < 4; jp++) {
                int cB = bcb + jp * 2;
                uint32_t bd = bbuf + bkk * 256 + ((cB ^ (bkk & 7)) << 4);
                uint32_t r0, r1, r2, r3;
                ldsm_x4t(r0, r1, r2, r3, bd);
#pragma unroll
                for (int i = 0; i < 2; i++) {
                    mma_f16(acc[i][jp * 2],     af[i], r0, r2);
                    mma_f16(acc[i][jp * 2 + 1], af[i], r1, r3);
                }
            }
        }
        st++; if (st == 3) st = 0;
    }

#pragma unroll
    for (int i = 0; i < 2; i++) {
        int row0 = bm * 128 + wm + i * 16 + g;
        int row1 = row0 + 8;
        size_t ro0 = (size_t)row0 * N;
        size_t ro1 = (size_t)row1 * N;
#pragma unroll
        for (int j = 0; j < 8; j++) {
            int col = bn * 128 + wn + j * 8 + 2 * t;
            float v0 = acc[i][j][0], v1 = acc[i][j][1];
            float v2 = acc[i][j][2], v3 = acc[i][j][3];
            if (bias) {
                float b0 = bias[col], b1 = bias[col + 1];
                v0 += b0; v1 += b1; v2 += b0; v3 += b1;
            }
            bool dg = (act == 1) || (act == 2 && col >= 3072);
            if (dg) {
                v0 = gelu_exact(v0); v1 = gelu_exact(v1);
                v2 = gelu_exact(v2); v3 = gelu_exact(v3);
            }
            if (resid) {
                v0 += resid[ro0 + col]; v1 += resid[ro0 + col + 1];
                v2 += resid[ro1 + col]; v3 += resid[ro1 + col + 1];
            }
            if (outh) {
                __half* C = (__half*)Cv;
                *(uint32_t*)&C[ro0 + col] = h2bits(v0, v1);
                *(uint32_t*)&C[ro1 + col] = h2bits(v2, v3);
            } else {
                float* C = (float*)Cv;
                *(float2*)&C[ro0 + col] = make_float2(v0, v1);
                *(float2*)&C[ro1 + col] = make_float2(v2, v3);
            }
        }
    }
}

// ---------------------------------------------------------------------------
// fp16 flash attention with double-buffered cp.async K/V (R12 version).
// QKV fp16 [BS][3584].  Mech factor applied post-MMA in fp32.
// smem: Q 16KB | K 2x8KB | V 2x8KB | fac 2x64 fl = 49664 B (dynamic).
// ---------------------------------------------------------------------------
__device__ __forceinline__ uint32_t aswz(int r, int c) {
    return (uint32_t)(r * 128 + ((c ^ ((r + (r >> 3)) & 7)) << 4));
}

__global__ void __launch_bounds__(256)
attn_h_k(const __half* __restrict__ QKV, const float* __restrict__ mech,
         __half* __restrict__ Octx)
{
    extern __shared__ __align__(16) unsigned char asmem[];
    const uint32_t sb = (uint32_t)__cvta_generic_to_shared(asmem);
    const uint32_t kb = sb + 16384;
    const uint32_t vb = sb + 32768;
    float* facs = (float*)(asmem + 49152);   // [2][64]

    const int tid = threadIdx.x;
    const int w = tid >> 5, l = tid & 31;
    const int g = l >> 2, t = l & 3;
    const int bh = blockIdx.y;
    const int b = bh >> 4, h = bh & 15;
    const int q0 = blockIdx.x * 128;
    const int qr = w * 16;

    {
        int r = tid >> 1;
        int c0 = (tid & 1) * 4;
        const __half* qp = QKV + ((size_t)(b * 1024 + q0 + r)) * NQKV + h * 64;
#pragma unroll
        for (int u = 0; u < 4; u++) {
            int c = c0 + u;
            uint4 v = *(const uint4*)(qp + c * 8);
            asm volatile("st.shared.v4.u32 [%0], {%1,%2,%3,%4};" ::
                         "r"(sb + aswz(r, c)), "r"(v.x), "r"(v.y), "r"(v.z), "r"(v.w));
        }
    }

    const int kvr = tid >> 2;
    const int kvc0 = (tid & 3) * 2;
    {
        size_t rowb = ((size_t)(b * 1024 + kvr)) * NQKV + h * 64;
#pragma unroll
        for (int u = 0; u < 2; u++) {
            int c = kvc0 + u;
            cp16(kb + aswz(kvr, c), QKV + rowb + 1024 + c * 8);
            cp16(vb + aswz(kvr, c), QKV + rowb + 2048 + c * 8);
        }
        cp_commit();
    }
    float facr = 0.f;
    if (tid < 64) facr = mech[(size_t)b * 1024 + tid];

    float m0 = -1e30f, m1 = -1e30f, l0 = 0.f, l1 = 0.f;
    float acc[8][4];
#pragma unroll
    for (int e = 0; e < 8; e++)
#pragma unroll
        for (int r = 0; r < 4; r++) acc[e][r] = 0.f;
    __syncthreads();

    for (int kt = 0; kt < 16; kt++) {
        cp_wait<0>();
        if (tid < 64) facs[(kt & 1) * 64 + tid] = 0.125f * (1.f + facr);
        __syncthreads();

        if (kt + 1 < 16) {
            const int nb = (kt + 1) & 1;
            size_t rowb = ((size_t)(b * 1024 + (kt + 1) * 64 + kvr)) * NQKV + h * 64;
#pragma unroll
            for (int u = 0; u < 2; u++) {
                int c = kvc0 + u;
                cp16(kb + nb * 8192 + aswz(kvr, c), QKV + rowb + 1024 + c * 8);
                cp16(vb + nb * 8192 + aswz(kvr, c), QKV + rowb + 2048 + c * 8);
            }
            cp_commit();
            if (tid < 64) facr = mech[(size_t)b * 1024 + (kt + 1) * 64 + tid];
        }

        const uint32_t kbuf = kb + (kt & 1) * 8192;
        const uint32_t vbuf = vb + (kt & 1) * 8192;
        const float* fac = facs + (kt & 1) * 64;

        float s[8][4];
#pragma unroll
        for (int j = 0; j < 8; j++)
#pragma unroll
            for (int r = 0; r < 4; r++) s[j][r] = 0.f;
#pragma unroll
        for (int kc = 0; kc < 4; kc++) {
            uint32_t a[4];
            {
                int row = qr + (l & 7) + ((l >> 3) & 1) * 8;
                int chunk = 2 * kc + (l >> 4);
                ldsm_x4(a[0], a[1], a[2], a[3], sb + aswz(row, chunk));
            }
#pragma unroll
            for (int jp = 0; jp < 4; jp++) {
                int key = jp * 16 + ((l >> 4) & 1) * 8 + (l & 7);
                int chunk = 2 * kc + ((l >> 3) & 1);
                uint32_t r0, r1, r2, r3;
                ldsm_x4(r0, r1, r2, r3, kbuf + aswz(key, chunk));
                mma_f16(s[jp * 2],     a, r0, r1);
                mma_f16(s[jp * 2 + 1], a, r2, r3);
            }
        }

#pragma unroll
        for (int j = 0; j < 8; j++) {
            float2 f = *(const float2*)&fac[j * 8 + 2 * t];
            s[j][0] *= f.x; s[j][1] *= f.y;
            s[j][2] *= f.x; s[j][3] *= f.y;
        }

        float mx0 = -1e30f, mx1 = -1e30f;
#pragma unroll
        for (int j = 0; j < 8; j++) {
            mx0 = fmaxf(mx0, fmaxf(s[j][0], s[j][1]));
            mx1 = fmaxf(mx1, fmaxf(s[j][2], s[j][3]));
        }
        mx0 = fmaxf(mx0, __shfl_xor_sync(0xffffffffu, mx0, 1));
        mx0 = fmaxf(mx0, __shfl_xor_sync(0xffffffffu, mx0, 2));
        mx1 = fmaxf(mx1, __shfl_xor_sync(0xffffffffu, mx1, 1));
        mx1 = fmaxf(mx1, __shfl_xor_sync(0xffffffffu, mx1, 2));
        float mn0 = fmaxf(m0, mx0), mn1 = fmaxf(m1, mx1);
        float al0 = __expf(m0 - mn0), al1 = __expf(m1 - mn1);
        float sum0 = 0.f, sum1 = 0.f;
#pragma unroll
        for (int j = 0; j < 8; j++) {
            s[j][0] = __expf(s[j][0] - mn0);
            s[j][1] = __expf(s[j][1] - mn0);
            s[j][2] = __expf(s[j][2] - mn1);
            s[j][3] = __expf(s[j][3] - mn1);
            sum0 += s[j][0] + s[j][1];
            sum1 += s[j][2] + s[j][3];
        }
        sum0 += __shfl_xor_sync(0xffffffffu, sum0, 1);
        sum0 += __shfl_xor_sync(0xffffffffu, sum0, 2);
        sum1 += __shfl_xor_sync(0xffffffffu, sum1, 1);
        sum1 += __shfl_xor_sync(0xffffffffu, sum1, 2);
        l0 = l0 * al0 + sum0;
        l1 = l1 * al1 + sum1;
        m0 = mn0; m1 = mn1;
#pragma unroll
        for (int e = 0; e < 8; e++) {
            acc[e][0] *= al0; acc[e][1] *= al0;
            acc[e][2] *= al1; acc[e][3] *= al1;
        }

#pragma unroll
        for (int u = 0; u < 4; u++) {
            uint32_t a[4];
            a[0] = h2bits(s[2 * u][0],     s[2 * u][1]);
            a[1] = h2bits(s[2 * u][2],     s[2 * u][3]);
            a[2] = h2bits(s[2 * u + 1][0], s[2 * u + 1][1]);
            a[3] = h2bits(s[2 * u + 1][2], s[2 * u + 1][3]);
#pragma unroll
            for (int ep = 0; ep < 4; ep++) {
                int key = u * 16 + ((l >> 3) & 1) * 8 + (l & 7);
                int chunk = ep * 2 + (l >> 4);
                uint32_t r0, r1, r2, r3;
                ldsm_x4t(r0, r1, r2, r3, vbuf + aswz(key, chunk));
                mma_f16(acc[ep * 2],     a, r0, r1);
                mma_f16(acc[ep * 2 + 1], a, r2, r3);
            }
        }
    }

    float inv0 = 1.f / l0, inv1 = 1.f / l1;
    size_t o0 = ((size_t)(b * 1024 + q0 + qr + g)) * 1024 + h * 64;
    size_t o1 = o0 + (size_t)8 * 1024;
#pragma unroll
    for (int e = 0; e < 8; e++) {
        *(uint32_t*)&Octx[o0 + e * 8 + 2 * t] = h2bits(acc[e][0] * inv0, acc[e][1] * inv0);
        *(uint32_t*)&Octx[o1 + e * 8 + 2 * t] = h2bits(acc[e][2] * inv1, acc[e][3] * inv1);
    }
}

// ---------------------------------------------------------------------------
// LayerNorm (1024) -> fp16. One block per row.
// ---------------------------------------------------------------------------
__global__ void layernorm_k(const float* __restrict__ x, const float* __restrict__ g,
                            const float* __restrict__ b, __half* __restrict__ o)
{
    int row = blockIdx.x;
    const float4* xr = (const float4*)(x + (size_t)row * 1024);
    float4 v = xr[threadIdx.x];
    float s  = v.x + v.y + v.z + v.w;
    float ss = fmaf(v.x, v.x, fmaf(v.y, v.y, fmaf(v.z, v.z, v.w * v.w)));
#pragma unroll
    for (int off = 16; off > 0; off >>= 1) {
        s  += __shfl_xor_sync(0xffffffffu, s,  off);
        ss += __shfl_xor_sync(0xffffffffu, ss, off);
    }
    __shared__ float ws[8], wss[8];
    __shared__ float s_mean, s_inv;
    int w = threadIdx.x >> 5, ln = threadIdx.x & 31;
    if (ln == 0) { ws[w] = s; wss[w] = ss; }
    __syncthreads();
    if (threadIdx.x == 0) {
        float S = 0.f, SS = 0.f;
#pragma unroll
        for (int i = 0; i < 8; i++) { S += ws[i]; SS += wss[i]; }
        float mean = S * (1.f / 1024.f);
        float var  = SS * (1.f / 1024.f) - mean * mean;
        s_mean = mean;
        s_inv  = rsqrtf(var + 1e-5f);
    }
    __syncthreads();
    float mean = s_mean, inv = s_inv;
    float4 gv = ((const float4*)g)[threadIdx.x];
    float4 bv = ((const float4*)b)[threadIdx.x];
    uint2 r;
    r.x = h2bits((v.x - mean) * inv * gv.x + bv.x, (v.y - mean) * inv * gv.y + bv.y);
    r.y = h2bits((v.z - mean) * inv * gv.z + bv.z, (v.w - mean) * inv * gv.w + bv.w);
    *(uint2*)&o[(size_t)row * 1024 + threadIdx.x * 4] = r;
}

// Fused: x = x_in + pep (write fp32 residual) AND layernorm(x) -> fp16.
__global__ void ln_addpe_k(const float* __restrict__ xin, const float* __restrict__ pep,
                           const float* __restrict__ g, const float* __restrict__ b,
                           float* __restrict__ xo, __half* __restrict__ o)
{
    int row = blockIdx.x;
    float4 xi = ((const float4*)(xin + (size_t)row * 1024))[threadIdx.x];
    float4 pe = ((const float4*)(pep + (size_t)(row & 1023) * 1024))[threadIdx.x];
    float4 v = make_float4(xi.x + pe.x, xi.y + pe.y, xi.z + pe.z, xi.w + pe.w);
    ((float4*)(xo + (size_t)row * 1024))[threadIdx.x] = v;
    float s  = v.x + v.y + v.z + v.w;
    float ss = fmaf(v.x, v.x, fmaf(v.y, v.y, fmaf(v.z, v.z, v.w * v.w)));
#pragma unroll
    for (int off = 16; off > 0; off >>= 1) {
        s  += __shfl_xor_sync(0xffffffffu, s,  off);
        ss += __shfl_xor_sync(0xffffffffu, ss, off);
    }
    __shared__ float ws[8], wss[8];
    __shared__ float s_mean, s_inv;
    int w = threadIdx.x >> 5, ln = threadIdx.x & 31;
    if (ln == 0) { ws[w] = s; wss[w] = ss; }
    __syncthreads();
    if (threadIdx.x == 0) {
        float S = 0.f, SS = 0.f;
#pragma unroll
        for (int i = 0; i < 8; i++) { S += ws[i]; SS += wss[i]; }
        float mean = S * (1.f / 1024.f);
        float var  = SS * (1.f / 1024.f) - mean * mean;
        s_mean = mean;
        s_inv  = rsqrtf(var + 1e-5f);
    }
    __syncthreads();
    float mean = s_mean, inv = s_inv;
    float4 gv = ((const float4*)g)[threadIdx.x];
    float4 bv = ((const float4*)b)[threadIdx.x];
    uint2 r;
    r.x = h2bits((v.x - mean) * inv * gv.x + bv.x, (v.y - mean) * inv * gv.y + bv.y);
    r.y = h2bits((v.z - mean) * inv * gv.z + bv.z, (v.w - mean) * inv * gv.w + bv.w);
    *(uint2*)&o[(size_t)row * 1024 + threadIdx.x * 4] = r;
}

// ---------------------------------------------------------------------------
// Prep kernels (vectorized)
// ---------------------------------------------------------------------------
// One launch converts wi | ow | fw1 | fw2 (10M elems) into g_w16 regions.
__global__ void cvtall_k(const float* __restrict__ wi, const float* __restrict__ ow,
                         const float* __restrict__ fw1, const float* __restrict__ fw2,
                         __half* __restrict__ w16)
{
    int i = blockIdx.x * blockDim.x + threadIdx.x;   // 10M/8 = 1310720 threads
    const int M8 = 131072;                            // 1M elems in 8-elem units
    const float* src;
    size_t dst;
    if (i < M8)               { src = wi  + (size_t)i * 8;             dst = W16_WI  + (size_t)i * 8; }
    else if (i < 2 * M8)      { src = ow  + (size_t)(i - M8) * 8;      dst = W16_OW  + (size_t)(i - M8) * 8; }
    else if (i < 6 * M8)      { src = fw1 + (size_t)(i - 2 * M8) * 8;  dst = W16_FW1 + (size_t)(i - 2 * M8) * 8; }
    else                      { src = fw2 + (size_t)(i - 6 * M8) * 8;  dst = W16_FW2 + (size_t)(i - 6 * M8) * 8; }
    float4 a = *(const float4*)src;
    float4 b = *(const float4*)(src + 4);
    *(uint4*)&w16[dst] = make_uint4(h2bits(a.x, a.y), h2bits(a.z, a.w),
                                    h2bits(b.x, b.y), h2bits(b.z, b.w));
}

__global__ void build_pe_k(const float* __restrict__ pos, const float* __restrict__ tim,
                           __half* __restrict__ pe)
{
    int i = (blockIdx.x * blockDim.x + threadIdx.x) * 4;   // S*D
    int s = i >> 10, d = i & 1023;
    const float* srcp = (d < 512) ? pos + s * 512 + d : tim + s * 512 + (d - 512);
    float4 v = *(const float4*)srcp;
    *(uint2*)&pe[i] = make_uint2(h2bits(v.x, v.y), h2bits(v.z, v.w));
}

__global__ void softmax5_k(const float* __restrict__ elw, float* __restrict__ wsm,
                           float* __restrict__ out_w)
{
    if (threadIdx.x == 0) {
        float m = elw[0];
        for (int p = 1; p < 5; p++) m = fmaxf(m, elw[p]);
        float e[5], s = 0.f;
        for (int p = 0; p < 5; p++) { e[p] = expf(elw[p] - m); s += e[p]; }
        float inv = 1.f / s;
        for (int p = 0; p < 5; p++) { wsm[p] = e[p] * inv; out_w[p] = e[p] * inv; }
    }
}

__global__ void combine_w5_k(const float* __restrict__ ew, const float* __restrict__ wsm,
                             __half* __restrict__ w5)
{
    int i = (blockIdx.x * blockDim.x + threadIdx.x) * 4;   // D*D
    float w0 = wsm[0], w1 = wsm[1], w2 = wsm[2], w3 = wsm[3], w4 = wsm[4];
    const size_t DD = (size_t)1024 * 1024;
    float4 e0 = *(const float4*)&ew[i];
    float4 e1 = *(const float4*)&ew[DD + i];
    float4 e2 = *(const float4*)&ew[2 * DD + i];
    float4 e3 = *(const float4*)&ew[3 * DD + i];
    float4 e4 = *(const float4*)&ew[4 * DD + i];
    float vx = w0 * e0.x + w1 * e1.x + w2 * e2.x + w3 * e3.x + w4 * e4.x;
    float vy = w0 * e0.y + w1 * e1.y + w2 * e2.y + w3 * e3.y + w4 * e4.y;
    float vz = w0 * e0.z + w1 * e1.z + w2 * e2.z + w3 * e3.z + w4 * e4.z;
    float vw = w0 * e0.w + w1 * e1.w + w2 * e2.w + w3 * e3.w + w4 * e4.w;
    *(uint2*)&w5[i] = make_uint2(h2bits(vx, vy), h2bits(vz, vw));
}

__global__ void combine_b5_k(const float* __restrict__ eb, const float* __restrict__ wsm,
                             float* __restrict__ b5)
{
    int i = blockIdx.x * blockDim.x + threadIdx.x;   // D
    float v = 0.f;
    for (int p = 0; p < 5; p++) v += wsm[p] * eb[p * 1024 + i];
    b5[i] = v;
}

// Pack qw|kw|vw|mw1 -> fp16 [D][3584]; biases -> fp32 [3584]. 8 cols/thread.
__global__ void pack_qkvm_k(const float* __restrict__ qw, const float* __restrict__ kw,
                            const float* __restrict__ vw, const float* __restrict__ mw1,
                            const float* __restrict__ qb, const float* __restrict__ kb,
                            const float* __restrict__ vb, const float* __restrict__ mb1,
                            __half* __restrict__ wq, float* __restrict__ bq)
{
    int i = blockIdx.x * blockDim.x + threadIdx.x;   // D * 448
    int k = i / 448, n = (i - k * 448) * 8;
    const float* sp;
    if (n < 1024)      sp = qw  + k * 1024 + n;
    else if (n < 2048) sp = kw  + k * 1024 + (n - 1024);
    else if (n < 3072) sp = vw  + k * 1024 + (n - 2048);
    else               sp = mw1 + k * 512  + (n - 3072);
    float4 a = *(const float4*)sp;
    float4 b = *(const float4*)(sp + 4);
    *(uint4*)&wq[(size_t)k * NQKV + n] =
        make_uint4(h2bits(a.x, a.y), h2bits(a.z, a.w), h2bits(b.x, b.y), h2bits(b.z, b.w));
    if (i < NQKV) {
        float bb;
        if (i < 1024)      bb = qb[i];
        else if (i < 2048) bb = kb[i - 1024];
        else if (i < 3072) bb = vb[i - 2048];
        else               bb = mb1[i - 3072];
        bq[i] = bb;
    }
}

// mech[r] = sigmoid(dot(qkv16[r, 3072:3584], mw2) + mb2); one warp per row.
__global__ void mech_out_k(const __half* __restrict__ qkv, const float* __restrict__ mw2,
                           const float* __restrict__ mb2, float* __restrict__ mech,
                           float* __restrict__ out_mech)
{
    int row  = blockIdx.x * 8 + (threadIdx.x >> 5);
    int lane = threadIdx.x & 31;
    const __half* r = qkv + (size_t)row * NQKV + 3072;
    float s = 0.f;
#pragma unroll
    for (int c = lane; c < 512; c += 32) s = fmaf(__half2float(r[c]), mw2[c], s);
#pragma unroll
    for (int off = 16; off > 0; off >>= 1) s += __shfl_xor_sync(0xffffffffu, s, off);
    if (lane == 0) {
        float t = s + mb2[0];
        float m = 1.f / (1.f + expf(-t));
        mech[row] = m;
        out_mech[row] = m;
    }
}

// ---------------------------------------------------------------------------
// Host launcher
// ---------------------------------------------------------------------------
extern "C" void kernel_launch(void* const* d_in, const int* in_sizes, int n_in,
                              void* d_out, int out_size)
{
    (void)in_sizes; (void)n_in; (void)out_size;
    const float* x_in = (const float*)d_in[0];
    const float* pos  = (const float*)d_in[1];
    const float* tim  = (const float*)d_in[2];
    const float* wi   = (const float*)d_in[3];
    const float* bi   = (const float*)d_in[4];
    const float* g1   = (const float*)d_in[5];
    const float* be1  = (const float*)d_in[6];
    const float* g2   = (const float*)d_in[7];
    const float* be2  = (const float*)d_in[8];
    const float* g3   = (const float*)d_in[9];
    const float* be3  = (const float*)d_in[10];
    const float* qw   = (const float*)d_in[11];
    const float* qb   = (const float*)d_in[12];
    const float* kw   = (const float*)d_in[13];
    const float* kb   = (const float*)d_in[14];
    const float* vw   = (const float*)d_in[15];
    const float* vb   = (const float*)d_in[16];
    const float* ow   = (const float*)d_in[17];
    const float* ob   = (const float*)d_in[18];
    const float* mw1  = (const float*)d_in[19];
    const float* mb1  = (const float*)d_in[20];
    const float* mw2  = (const float*)d_in[21];
    const float* mb2  = (const float*)d_in[22];
    const float* ew   = (const float*)d_in[23];
    const float* eb   = (const float*)d_in[24];
    const float* elw  = (const float*)d_in[25];
    const float* fw1  = (const float*)d_in[26];
    const float* fb1  = (const float*)d_in[27];
    const float* fw2  = (const float*)d_in[28];
    const float* fb2  = (const float*)d_in[29];

    float* out = (float*)d_out;
    float* out_mech = out + NXD;
    float* out_w    = out + NXD + BS;

    float* fb = nullptr;
    cudaGetSymbolAddress((void**)&fb, g_buf);
    float* gx    = fb + OFF_X;
    float* gpep  = fb + OFF_PEP;
    float* gmech = fb + OFF_MECH;
    float* gb5   = fb + OFF_B5;
    float* gwsm  = fb + OFF_WSM;
    float* gbqkv = fb + OFF_BQKV;

    __half *h16, *qkv16, *ctx16, *ffh16, *pe16, *w16;
    cudaGetSymbolAddress((void**)&h16,   g_h16);
    cudaGetSymbolAddress((void**)&qkv16, g_qkv16);
    cudaGetSymbolAddress((void**)&ctx16, g_ctx16);
    cudaGetSymbolAddress((void**)&ffh16, g_ffh16);
    cudaGetSymbolAddress((void**)&pe16,  g_pe16);
    cudaGetSymbolAddress((void**)&w16,   g_w16);

    const int GEMM_SMEM = 98304;   // 3 x 32KB stages
    cudaFuncSetAttribute(hgemm_k, cudaFuncAttributeMaxDynamicSharedMemorySize, GEMM_SMEM);
    const int ATTN_SMEM = 49664;
    cudaFuncSetAttribute(attn_h_k, cudaFuncAttributeMaxDynamicSharedMemorySize, ATTN_SMEM);

    // weight conversions (fp32 -> fp16), single fused launch + QKV pack
    cvtall_k<<<(10 * 1024 * 1024 / 8) / 256, 256>>>(wi, ow, fw1, fw2, w16);
    pack_qkvm_k<<<(Dc * 448) / 256, 256>>>(qw, kw, vw, mw1, qb, kb, vb, mb1,
                                           w16 + W16_QKV, gbqkv);

    // 1) positional/timing embedding
    build_pe_k<<<(Sc * Dc / 4) / 256, 256>>>(pos, tim, pe16);
    hgemm_k<<<dim3(Dc / 128, Sc / 128), 256, GEMM_SMEM>>>(pe16, w16 + W16_WI, bi, nullptr,
                                                          gpep, Sc, Dc, Dc, 0, 0);
    // 2) x = x_in + pep; norm1 -> h16  (fused)
    ln_addpe_k<<<BS, 256>>>(x_in, gpep, g1, be1, gx, h16);

    // 3) fused QKV + mech-hidden projection (fp16 out)
    hgemm_k<<<dim3(NQKV / 128, BS / 128), 256, GEMM_SMEM>>>(h16, w16 + W16_QKV, gbqkv,
                                                            nullptr, qkv16, BS, NQKV, Dc, 2, 1);

    // 4) mechanism output
    mech_out_k<<<BS / 8, 256>>>(qkv16, mw2, mb2, gmech, out_mech);

    // 5) fp16 flash attention -> ctx16
    attn_h_k<<<dim3(Sc / 128, Bc * Hc), 256, ATTN_SMEM>>>(qkv16, gmech, ctx16);

    // 6) output projection + residual
    hgemm_k<<<dim3(Dc / 128, BS / 128), 256, GEMM_SMEM>>>(ctx16, w16 + W16_OW, ob, gx,
                                                          gx, BS, Dc, Dc, 0, 0);

    // 7) five elements (folded to one GEMM)
    layernorm_k<<<BS, 256>>>(gx, g2, be2, h16);
    softmax5_k<<<1, 32>>>(elw, gwsm, out_w);
    combine_w5_k<<<(Dc * Dc / 4) / 256, 256>>>(ew, gwsm, w16 + W16_W5);
    combine_b5_k<<<Dc / 256, 256>>>(eb, gwsm, gb5);
    hgemm_k<<<dim3(Dc / 128, BS / 128), 256, GEMM_SMEM>>>(h16, w16 + W16_W5, gb5, gx,
                                                          gx, BS, Dc, Dc, 0, 0);

    // 8) FFN
    layernorm_k<<<BS, 256>>>(gx, g3, be3, h16);
    hgemm_k<<<dim3(DFFc / 128, BS / 128), 256, GEMM_SMEM>>>(h16, w16 + W16_FW1, fb1, nullptr,
                                                            ffh16, BS, DFFc, Dc, 1, 1);
    hgemm_k<<<dim3(Dc / 128, BS / 128), 256, GEMM_SMEM>>>(ffh16, w16 + W16_FW2, fb2, gx,
                                                          out, BS, Dc, DFFc, 0, 0);
}

// round 16
// speedup vs baseline: 1.1753x; 1.0012x over previous
#include <cuda_runtime.h>
#include <cuda_fp16.h>
#include <math.h>
#include <stdint.h>

// ---------------------------------------------------------------------------
// MechanismTransformerBlock  B=8 S=1024 D=1024 H=16 DH=64 DFF=4096
// fp16 tensor-core path (128x128 tile, 256 thr, 2 CTAs/SM):
//  - hgemm: BK=64 (four 4KB subtiles/stage), 3-stage cp.async ring (dyn smem)
//  - attention: double-buffered cp.async K/V, mech factor applied post-MMA
// ---------------------------------------------------------------------------

namespace {
constexpr int Bc = 8, Sc = 1024, Dc = 1024, Hc = 16, DFFc = 4096;
constexpr int BS = Bc * Sc;                       // 8192 rows
constexpr size_t NXD = (size_t)BS * Dc;           // 8,388,608
constexpr int NQKV = 3584;                        // q|k|v|mech-hidden

// fp32 scratch
constexpr size_t OFF_X    = 0;
constexpr size_t OFF_PEP  = OFF_X   + NXD;                    // S x D
constexpr size_t OFF_MECH = OFF_PEP + (size_t)Sc * Dc;        // BS
constexpr size_t OFF_B5   = OFF_MECH+ (size_t)BS;             // D
constexpr size_t OFF_WSM  = OFF_B5  + Dc;                     // 8
constexpr size_t OFF_BQKV = OFF_WSM + 8;                      // 3584
constexpr size_t TOTALF   = OFF_BQKV + NQKV;

// fp16 weight staging offsets (in halfs)
constexpr size_t W16_WI  = 0;
constexpr size_t W16_OW  = W16_WI  + (size_t)Dc * Dc;
constexpr size_t W16_W5  = W16_OW  + (size_t)Dc * Dc;
constexpr size_t W16_FW1 = W16_W5  + (size_t)Dc * Dc;
constexpr size_t W16_FW2 = W16_FW1 + (size_t)Dc * DFFc;
constexpr size_t W16_QKV = W16_FW2 + (size_t)DFFc * Dc;
constexpr size_t W16_TOT = W16_QKV + (size_t)Dc * NQKV;
}

__device__ float  g_buf[TOTALF];
__device__ __half g_h16[NXD];                 // LN output
__device__ __half g_qkv16[(size_t)BS * NQKV]; // q|k|v|mech-hidden
__device__ __half g_ctx16[NXD];               // attention output
__device__ __half g_ffh16[(size_t)BS * DFFc]; // FFN hidden
__device__ __half g_pe16[(size_t)Sc * Dc];
__device__ __half g_w16[W16_TOT];

__device__ __forceinline__ float gelu_exact(float v) {
    return 0.5f * v * (1.0f + erff(v * 0.70710678118654752440f));
}

__device__ __forceinline__ void mma_f16(float* c, const uint32_t* a, uint32_t b0, uint32_t b1) {
    asm volatile(
        "mma.sync.aligned.m16n8k16.row.col.f32.f16.f16.f32 "
        "{%0,%1,%2,%3}, {%4,%5,%6,%7}, {%8,%9}, {%0,%1,%2,%3};\n"
        : "+f"(c[0]), "+f"(c[1]), "+f"(c[2]), "+f"(c[3])
        : "r"(a[0]), "r"(a[1]), "r"(a[2]), "r"(a[3]), "r"(b0), "r"(b1));
}

__device__ __forceinline__ void ldsm_x4(uint32_t& r0, uint32_t& r1, uint32_t& r2, uint32_t& r3,
                                        uint32_t addr) {
    asm volatile("ldmatrix.sync.aligned.m8n8.x4.shared.b16 {%0,%1,%2,%3}, [%4];"
                 : "=r"(r0), "=r"(r1), "=r"(r2), "=r"(r3) : "r"(addr));
}

__device__ __forceinline__ void ldsm_x4t(uint32_t& r0, uint32_t& r1, uint32_t& r2, uint32_t& r3,
                                         uint32_t addr) {
    asm volatile("ldmatrix.sync.aligned.m8n8.x4.trans.shared.b16 {%0,%1,%2,%3}, [%4];"
                 : "=r"(r0), "=r"(r1), "=r"(r2), "=r"(r3) : "r"(addr));
}

__device__ __forceinline__ uint32_t h2bits(float lo, float hi) {
    __half2 h = __floats2half2_rn(lo, hi);
    return *reinterpret_cast<uint32_t*>(&h);
}

__device__ __forceinline__ void cp16(uint32_t smem, const void* g) {
    asm volatile("cp.async.cg.shared.global [%0], [%1], 16;" :: "r"(smem), "l"(g));
}
__device__ __forceinline__ void cp_commit() {
    asm volatile("cp.async.commit_group;");
}
template <int N>
__device__ __forceinline__ void cp_wait() {
    asm volatile("cp.async.wait_group %0;" :: "n"(N));
}

// ---------------------------------------------------------------------------
// fp16 GEMM, 3-stage cp.async pipeline, BK=64 (dynamic smem 96KB).
// 128x128 tile, 256 thr = 8 warps (4M x 2N), warp tile 32x64.
// Stage (32KB) = A subtiles ks=0..3 (4KB each, [m][16] swz c^((m>>2)&1))
//              + B subtiles ks=0..3 (4KB each, [k][128] swz c^(k&7)) at +16KB.
// act: 0 none, 1 gelu, 2 gelu iff global col >= 3072.  K % 64 == 0.
// ---------------------------------------------------------------------------
__global__ void __launch_bounds__(256, 2)
hgemm_k(const __half* __restrict__ A, const __half* __restrict__ Bm,
        const float* __restrict__ bias, const float* __restrict__ resid,
        void* __restrict__ Cv, int M, int N, int K, int act, int outh)
{
    extern __shared__ __align__(16) unsigned char hsm[];
    const uint32_t smem_base = (uint32_t)__cvta_generic_to_shared(hsm);

    const int tid = threadIdx.x;
    const int w = tid >> 5, l = tid & 31;
    const int wm = (w & 3) * 32;
    const int wn = (w >> 2) * 64;
    const int g = l >> 2, t = l & 3;
    const int bn = blockIdx.x, bm = blockIdx.y;
    const __half* Ab = A + (size_t)bm * 128 * K;
    const __half* Bb = Bm + (size_t)bn * 128;

    const int arow = tid >> 1;            // 0..127
    const int ac   = tid & 1;
    const int brow = tid >> 4;            // 0..15
    const int bc   = tid & 15;

    const uint32_t a_st = smem_base + arow * 32 + ((ac ^ ((arow >> 2) & 1)) << 4);
    const uint32_t b_st = smem_base + 16384 + brow * 256 + ((bc ^ (brow & 7)) << 4);
    const __half* a_gp = Ab + (size_t)arow * K + ac * 8;
    const __half* b_gp = Bb + (size_t)brow * N + bc * 8;

    const int amr = ((l >> 3) & 1) * 8 + (l & 7);
    const int acf = l >> 4;
    const int bkk = ((l >> 4) & 1) * 8 + (l & 7);
    const int bcb = (wn >> 3) + ((l >> 3) & 1);

    const int NIT = K >> 6;

    float acc[2][8][4];
#pragma unroll
    for (int i = 0; i < 2; i++)
#pragma unroll
        for (int j = 0; j < 8; j++)
#pragma unroll
            for (int r = 0; r < 4; r++) acc[i][j][r] = 0.f;

    // prologue: stages 0,1 (each = k tile of 64)
#pragma unroll
    for (int s = 0; s < 2; s++) {
#pragma unroll
        for (int ks = 0; ks < 4; ks++) {
            cp16(a_st + s * 32768 + ks * 4096, a_gp + s * 64 + ks * 16);
            cp16(b_st + s * 32768 + ks * 4096, b_gp + (size_t)(s * 64 + ks * 16) * N);
        }
        cp_commit();
    }

    int st = 0;
    for (int it = 0; it < NIT; it++) {
        cp_wait<1>();            // stage it arrived
        __syncthreads();         // stage (it+2)%3 provably drained
        {
            int nx = it + 2;
            if (nx < NIT) {
                int ring = nx - (nx / 3) * 3;
#pragma unroll
                for (int ks = 0; ks < 4; ks++) {
                    cp16(a_st + ring * 32768 + ks * 4096, a_gp + nx * 64 + ks * 16);
                    cp16(b_st + ring * 32768 + ks * 4096,
                         b_gp + (size_t)(nx * 64 + ks * 16) * N);
                }
            }
            cp_commit();
        }
#pragma unroll
        for (int ks = 0; ks < 4; ks++) {
            const uint32_t abuf = smem_base + st * 32768 + ks * 4096;
            const uint32_t bbuf = smem_base + 16384 + st * 32768 + ks * 4096;
            uint32_t af[2][4];
#pragma unroll
            for (int i = 0; i < 2; i++) {
                int m = wm + i * 16 + amr;
                uint32_t ad = abuf + m * 32 + ((acf ^ ((m >> 2) & 1)) << 4);
                ldsm_x4(af[i][0], af[i][1], af[i][2], af[i][3], ad);
            }
#pragma unroll
            for (int jp = 0; jp < 4; jp++) {
                int cB = bcb + jp * 2;
                uint32_t bd = bbuf + bkk * 256 + ((cB ^ (bkk & 7)) << 4);
                uint32_t r0, r1, r2, r3;
                ldsm_x4t(r0, r1, r2, r3, bd);
#pragma unroll
                for (int i = 0; i < 2; i++) {
                    mma_f16(acc[i][jp * 2],     af[i], r0, r2);
                    mma_f16(acc[i][jp * 2 + 1], af[i], r1, r3);
                }
            }
        }
        st++; if (st == 3) st = 0;
    }

#pragma unroll
    for (int i = 0; i < 2; i++) {
        int row0 = bm * 128 + wm + i * 16 + g;
        int row1 = row0 + 8;
        size_t ro0 = (size_t)row0 * N;
        size_t ro1 = (size_t)row1 * N;
#pragma unroll
        for (int j = 0; j < 8; j++) {
            int col = bn * 128 + wn + j * 8 + 2 * t;
            float v0 = acc[i][j][0], v1 = acc[i][j][1];
            float v2 = acc[i][j][2], v3 = acc[i][j][3];
            if (bias) {
                float b0 = bias[col], b1 = bias[col + 1];
                v0 += b0; v1 += b1; v2 += b0; v3 += b1;
            }
            bool dg = (act == 1) || (act == 2 && col >= 3072);
            if (dg) {
                v0 = gelu_exact(v0); v1 = gelu_exact(v1);
                v2 = gelu_exact(v2); v3 = gelu_exact(v3);
            }
            if (resid) {
                v0 += resid[ro0 + col]; v1 += resid[ro0 + col + 1];
                v2 += resid[ro1 + col]; v3 += resid[ro1 + col + 1];
            }
            if (outh) {
                __half* C = (__half*)Cv;
                *(uint32_t*)&C[ro0 + col] = h2bits(v0, v1);
                *(uint32_t*)&C[ro1 + col] = h2bits(v2, v3);
            } else {
                float* C = (float*)Cv;
                *(float2*)&C[ro0 + col] = make_float2(v0, v1);
                *(float2*)&C[ro1 + col] = make_float2(v2, v3);
            }
        }
    }
}

// ---------------------------------------------------------------------------
// fp16 flash attention with double-buffered cp.async K/V (R12 version).
// QKV fp16 [BS][3584].  Mech factor applied post-MMA in fp32.
// smem: Q 16KB | K 2x8KB | V 2x8KB | fac 2x64 fl = 49664 B (dynamic).
// ---------------------------------------------------------------------------
__device__ __forceinline__ uint32_t aswz(int r, int c) {
    return (uint32_t)(r * 128 + ((c ^ ((r + (r >> 3)) & 7)) << 4));
}

__global__ void __launch_bounds__(256)
attn_h_k(const __half* __restrict__ QKV, const float* __restrict__ mech,
         __half* __restrict__ Octx)
{
    extern __shared__ __align__(16) unsigned char asmem[];
    const uint32_t sb = (uint32_t)__cvta_generic_to_shared(asmem);
    const uint32_t kb = sb + 16384;
    const uint32_t vb = sb + 32768;
    float* facs = (float*)(asmem + 49152);   // [2][64]

    const int tid = threadIdx.x;
    const int w = tid >> 5, l = tid & 31;
    const int g = l >> 2, t = l & 3;
    const int bh = blockIdx.y;
    const int b = bh >> 4, h = bh & 15;
    const int q0 = blockIdx.x * 128;
    const int qr = w * 16;

    {
        int r = tid >> 1;
        int c0 = (tid & 1) * 4;
        const __half* qp = QKV + ((size_t)(b * 1024 + q0 + r)) * NQKV + h * 64;
#pragma unroll
        for (int u = 0; u < 4; u++) {
            int c = c0 + u;
            uint4 v = *(const uint4*)(qp + c * 8);
            asm volatile("st.shared.v4.u32 [%0], {%1,%2,%3,%4};" ::
                         "r"(sb + aswz(r, c)), "r"(v.x), "r"(v.y), "r"(v.z), "r"(v.w));
        }
    }

    const int kvr = tid >> 2;
    const int kvc0 = (tid & 3) * 2;
    {
        size_t rowb = ((size_t)(b * 1024 + kvr)) * NQKV + h * 64;
#pragma unroll
        for (int u = 0; u < 2; u++) {
            int c = kvc0 + u;
            cp16(kb + aswz(kvr, c), QKV + rowb + 1024 + c * 8);
            cp16(vb + aswz(kvr, c), QKV + rowb + 2048 + c * 8);
        }
        cp_commit();
    }
    float facr = 0.f;
    if (tid < 64) facr = mech[(size_t)b * 1024 + tid];

    float m0 = -1e30f, m1 = -1e30f, l0 = 0.f, l1 = 0.f;
    float acc[8][4];
#pragma unroll
    for (int e = 0; e < 8; e++)
#pragma unroll
        for (int r = 0; r < 4; r++) acc[e][r] = 0.f;
    __syncthreads();

    for (int kt = 0; kt < 16; kt++) {
        cp_wait<0>();
        if (tid < 64) facs[(kt & 1) * 64 + tid] = 0.125f * (1.f + facr);
        __syncthreads();

        if (kt + 1 < 16) {
            const int nb = (kt + 1) & 1;
            size_t rowb = ((size_t)(b * 1024 + (kt + 1) * 64 + kvr)) * NQKV + h * 64;
#pragma unroll
            for (int u = 0; u < 2; u++) {
                int c = kvc0 + u;
                cp16(kb + nb * 8192 + aswz(kvr, c), QKV + rowb + 1024 + c * 8);
                cp16(vb + nb * 8192 + aswz(kvr, c), QKV + rowb + 2048 + c * 8);
            }
            cp_commit();
            if (tid < 64) facr = mech[(size_t)b * 1024 + (kt + 1) * 64 + tid];
        }

        const uint32_t kbuf = kb + (kt & 1) * 8192;
        const uint32_t vbuf = vb + (kt & 1) * 8192;
        const float* fac = facs + (kt & 1) * 64;

        float s[8][4];
#pragma unroll
        for (int j = 0; j < 8; j++)
#pragma unroll
            for (int r = 0; r < 4; r++) s[j][r] = 0.f;
#pragma unroll
        for (int kc = 0; kc < 4; kc++) {
            uint32_t a[4];
            {
                int row = qr + (l & 7) + ((l >> 3) & 1) * 8;
                int chunk = 2 * kc + (l >> 4);
                ldsm_x4(a[0], a[1], a[2], a[3], sb + aswz(row, chunk));
            }
#pragma unroll
            for (int jp = 0; jp < 4; jp++) {
                int key = jp * 16 + ((l >> 4) & 1) * 8 + (l & 7);
                int chunk = 2 * kc + ((l >> 3) & 1);
                uint32_t r0, r1, r2, r3;
                ldsm_x4(r0, r1, r2, r3, kbuf + aswz(key, chunk));
                mma_f16(s[jp * 2],     a, r0, r1);
                mma_f16(s[jp * 2 + 1], a, r2, r3);
            }
        }

#pragma unroll
        for (int j = 0; j < 8; j++) {
            float2 f = *(const float2*)&fac[j * 8 + 2 * t];
            s[j][0] *= f.x; s[j][1] *= f.y;
            s[j][2] *= f.x; s[j][3] *= f.y;
        }

        float mx0 = -1e30f, mx1 = -1e30f;
#pragma unroll
        for (int j = 0; j < 8; j++) {
            mx0 = fmaxf(mx0, fmaxf(s[j][0], s[j][1]));
            mx1 = fmaxf(mx1, fmaxf(s[j][2], s[j][3]));
        }
        mx0 = fmaxf(mx0, __shfl_xor_sync(0xffffffffu, mx0, 1));
        mx0 = fmaxf(mx0, __shfl_xor_sync(0xffffffffu, mx0, 2));
        mx1 = fmaxf(mx1, __shfl_xor_sync(0xffffffffu, mx1, 1));
        mx1 = fmaxf(mx1, __shfl_xor_sync(0xffffffffu, mx1, 2));
        float mn0 = fmaxf(m0, mx0), mn1 = fmaxf(m1, mx1);
        float al0 = __expf(m0 - mn0), al1 = __expf(m1 - mn1);
        float sum0 = 0.f, sum1 = 0.f;
#pragma unroll
        for (int j = 0; j < 8; j++) {
            s[j][0] = __expf(s[j][0] - mn0);
            s[j][1] = __expf(s[j][1] - mn0);
            s[j][2] = __expf(s[j][2] - mn1);
            s[j][3] = __expf(s[j][3] - mn1);
            sum0 += s[j][0] + s[j][1];
            sum1 += s[j][2] + s[j][3];
        }
        sum0 += __shfl_xor_sync(0xffffffffu, sum0, 1);
        sum0 += __shfl_xor_sync(0xffffffffu, sum0, 2);
        sum1 += __shfl_xor_sync(0xffffffffu, sum1, 1);
        sum1 += __shfl_xor_sync(0xffffffffu, sum1, 2);
        l0 = l0 * al0 + sum0;
        l1 = l1 * al1 + sum1;
        m0 = mn0; m1 = mn1;
#pragma unroll
        for (int e = 0; e < 8; e++) {
            acc[e][0] *= al0; acc[e][1] *= al0;
            acc[e][2] *= al1; acc[e][3] *= al1;
        }

#pragma unroll
        for (int u = 0; u < 4; u++) {
            uint32_t a[4];
            a[0] = h2bits(s[2 * u][0],     s[2 * u][1]);
            a[1] = h2bits(s[2 * u][2],     s[2 * u][3]);
            a[2] = h2bits(s[2 * u + 1][0], s[2 * u + 1][1]);
            a[3] = h2bits(s[2 * u + 1][2], s[2 * u + 1][3]);
#pragma unroll
            for (int ep = 0; ep < 4; ep++) {
                int key = u * 16 + ((l >> 3) & 1) * 8 + (l & 7);
                int chunk = ep * 2 + (l >> 4);
                uint32_t r0, r1, r2, r3;
                ldsm_x4t(r0, r1, r2, r3, vbuf + aswz(key, chunk));
                mma_f16(acc[ep * 2],     a, r0, r1);
                mma_f16(acc[ep * 2 + 1], a, r2, r3);
            }
        }
    }

    float inv0 = 1.f / l0, inv1 = 1.f / l1;
    size_t o0 = ((size_t)(b * 1024 + q0 + qr + g)) * 1024 + h * 64;
    size_t o1 = o0 + (size_t)8 * 1024;
#pragma unroll
    for (int e = 0; e < 8; e++) {
        *(uint32_t*)&Octx[o0 + e * 8 + 2 * t] = h2bits(acc[e][0] * inv0, acc[e][1] * inv0);
        *(uint32_t*)&Octx[o1 + e * 8 + 2 * t] = h2bits(acc[e][2] * inv1, acc[e][3] * inv1);
    }
}

// ---------------------------------------------------------------------------
// LayerNorm (1024) -> fp16. One block per row.
// ---------------------------------------------------------------------------
__global__ void layernorm_k(const float* __restrict__ x, const float* __restrict__ g,
                            const float* __restrict__ b, __half* __restrict__ o)
{
    int row = blockIdx.x;
    const float4* xr = (const float4*)(x + (size_t)row * 1024);
    float4 v = xr[threadIdx.x];
    float s  = v.x + v.y + v.z + v.w;
    float ss = fmaf(v.x, v.x, fmaf(v.y, v.y, fmaf(v.z, v.z, v.w * v.w)));
#pragma unroll
    for (int off = 16; off > 0; off >>= 1) {
        s  += __shfl_xor_sync(0xffffffffu, s,  off);
        ss += __shfl_xor_sync(0xffffffffu, ss, off);
    }
    __shared__ float ws[8], wss[8];
    __shared__ float s_mean, s_inv;
    int w = threadIdx.x >> 5, ln = threadIdx.x & 31;
    if (ln == 0) { ws[w] = s; wss[w] = ss; }
    __syncthreads();
    if (threadIdx.x == 0) {
        float S = 0.f, SS = 0.f;
#pragma unroll
        for (int i = 0; i < 8; i++) { S += ws[i]; SS += wss[i]; }
        float mean = S * (1.f / 1024.f);
        float var  = SS * (1.f / 1024.f) - mean * mean;
        s_mean = mean;
        s_inv  = rsqrtf(var + 1e-5f);
    }
    __syncthreads();
    float mean = s_mean, inv = s_inv;
    float4 gv = ((const float4*)g)[threadIdx.x];
    float4 bv = ((const float4*)b)[threadIdx.x];
    uint2 r;
    r.x = h2bits((v.x - mean) * inv * gv.x + bv.x, (v.y - mean) * inv * gv.y + bv.y);
    r.y = h2bits((v.z - mean) * inv * gv.z + bv.z, (v.w - mean) * inv * gv.w + bv.w);
    *(uint2*)&o[(size_t)row * 1024 + threadIdx.x * 4] = r;
}

// Fused: x = x_in + pep (write fp32 residual) AND layernorm(x) -> fp16.
__global__ void ln_addpe_k(const float* __restrict__ xin, const float* __restrict__ pep,
                           const float* __restrict__ g, const float* __restrict__ b,
                           float* __restrict__ xo, __half* __restrict__ o)
{
    int row = blockIdx.x;
    float4 xi = ((const float4*)(xin + (size_t)row * 1024))[threadIdx.x];
    float4 pe = ((const float4*)(pep + (size_t)(row & 1023) * 1024))[threadIdx.x];
    float4 v = make_float4(xi.x + pe.x, xi.y + pe.y, xi.z + pe.z, xi.w + pe.w);
    ((float4*)(xo + (size_t)row * 1024))[threadIdx.x] = v;
    float s  = v.x + v.y + v.z + v.w;
    float ss = fmaf(v.x, v.x, fmaf(v.y, v.y, fmaf(v.z, v.z, v.w * v.w)));
#pragma unroll
    for (int off = 16; off > 0; off >>= 1) {
        s  += __shfl_xor_sync(0xffffffffu, s,  off);
        ss += __shfl_xor_sync(0xffffffffu, ss, off);
    }
    __shared__ float ws[8], wss[8];
    __shared__ float s_mean, s_inv;
    int w = threadIdx.x >> 5, ln = threadIdx.x & 31;
    if (ln == 0) { ws[w] = s; wss[w] = ss; }
    __syncthreads();
    if (threadIdx.x == 0) {
        float S = 0.f, SS = 0.f;
#pragma unroll
        for (int i = 0; i < 8; i++) { S += ws[i]; SS += wss[i]; }
        float mean = S * (1.f / 1024.f);
        float var  = SS * (1.f / 1024.f) - mean * mean;
        s_mean = mean;
        s_inv  = rsqrtf(var + 1e-5f);
    }
    __syncthreads();
    float mean = s_mean, inv = s_inv;
    float4 gv = ((const float4*)g)[threadIdx.x];
    float4 bv = ((const float4*)b)[threadIdx.x];
    uint2 r;
    r.x = h2bits((v.x - mean) * inv * gv.x + bv.x, (v.y - mean) * inv * gv.y + bv.y);
    r.y = h2bits((v.z - mean) * inv * gv.z + bv.z, (v.w - mean) * inv * gv.w + bv.w);
    *(uint2*)&o[(size_t)row * 1024 + threadIdx.x * 4] = r;
}

// ---------------------------------------------------------------------------
// Prep kernels (vectorized)
// ---------------------------------------------------------------------------
// One launch converts wi | ow | fw1 | fw2 (10M elems) into g_w16 regions.
__global__ void cvtall_k(const float* __restrict__ wi, const float* __restrict__ ow,
                         const float* __restrict__ fw1, const float* __restrict__ fw2,
                         __half* __restrict__ w16)
{
    int i = blockIdx.x * blockDim.x + threadIdx.x;   // 10M/8 = 1310720 threads
    const int M8 = 131072;                            // 1M elems in 8-elem units
    const float* src;
    size_t dst;
    if (i < M8)               { src = wi  + (size_t)i * 8;             dst = W16_WI  + (size_t)i * 8; }
    else if (i < 2 * M8)      { src = ow  + (size_t)(i - M8) * 8;      dst = W16_OW  + (size_t)(i - M8) * 8; }
    else if (i < 6 * M8)      { src = fw1 + (size_t)(i - 2 * M8) * 8;  dst = W16_FW1 + (size_t)(i - 2 * M8) * 8; }
    else                      { src = fw2 + (size_t)(i - 6 * M8) * 8;  dst = W16_FW2 + (size_t)(i - 6 * M8) * 8; }
    float4 a = *(const float4*)src;
    float4 b = *(const float4*)(src + 4);
    *(uint4*)&w16[dst] = make_uint4(h2bits(a.x, a.y), h2bits(a.z, a.w),
                                    h2bits(b.x, b.y), h2bits(b.z, b.w));
}

__global__ void build_pe_k(const float* __restrict__ pos, const float* __restrict__ tim,
                           __half* __restrict__ pe)
{
    int i = (blockIdx.x * blockDim.x + threadIdx.x) * 4;   // S*D
    int s = i >> 10, d = i & 1023;
    const float* srcp = (d < 512) ? pos + s * 512 + d : tim + s * 512 + (d - 512);
    float4 v = *(const float4*)srcp;
    *(uint2*)&pe[i] = make_uint2(h2bits(v.x, v.y), h2bits(v.z, v.w));
}

__global__ void softmax5_k(const float* __restrict__ elw, float* __restrict__ wsm,
                           float* __restrict__ out_w)
{
    if (threadIdx.x == 0) {
        float m = elw[0];
        for (int p = 1; p < 5; p++) m = fmaxf(m, elw[p]);
        float e[5], s = 0.f;
        for (int p = 0; p < 5; p++) { e[p] = expf(elw[p] - m); s += e[p]; }
        float inv = 1.f / s;
        for (int p = 0; p < 5; p++) { wsm[p] = e[p] * inv; out_w[p] = e[p] * inv; }
    }
}

__global__ void combine_w5_k(const float* __restrict__ ew, const float* __restrict__ wsm,
                             __half* __restrict__ w5)
{
    int i = (blockIdx.x * blockDim.x + threadIdx.x) * 4;   // D*D
    float w0 = wsm[0], w1 = wsm[1], w2 = wsm[2], w3 = wsm[3], w4 = wsm[4];
    const size_t DD = (size_t)1024 * 1024;
    float4 e0 = *(const float4*)&ew[i];
    float4 e1 = *(const float4*)&ew[DD + i];
    float4 e2 = *(const float4*)&ew[2 * DD + i];
    float4 e3 = *(const float4*)&ew[3 * DD + i];
    float4 e4 = *(const float4*)&ew[4 * DD + i];
    float vx = w0 * e0.x + w1 * e1.x + w2 * e2.x + w3 * e3.x + w4 * e4.x;
    float vy = w0 * e0.y + w1 * e1.y + w2 * e2.y + w3 * e3.y + w4 * e4.y;
    float vz = w0 * e0.z + w1 * e1.z + w2 * e2.z + w3 * e3.z + w4 * e4.z;
    float vw = w0 * e0.w + w1 * e1.w + w2 * e2.w + w3 * e3.w + w4 * e4.w;
    *(uint2*)&w5[i] = make_uint2(h2bits(vx, vy), h2bits(vz, vw));
}

__global__ void combine_b5_k(const float* __restrict__ eb, const float* __restrict__ wsm,
                             float* __restrict__ b5)
{
    int i = blockIdx.x * blockDim.x + threadIdx.x;   // D
    float v = 0.f;
    for (int p = 0; p < 5; p++) v += wsm[p] * eb[p * 1024 + i];
    b5[i] = v;
}

// Pack qw|kw|vw|mw1 -> fp16 [D][3584]; biases -> fp32 [3584]. 8 cols/thread.
__global__ void pack_qkvm_k(const float* __restrict__ qw, const float* __restrict__ kw,
                            const float* __restrict__ vw, const float* __restrict__ mw1,
                            const float* __restrict__ qb, const float* __restrict__ kb,
                            const float* __restrict__ vb, const float* __restrict__ mb1,
                            __half* __restrict__ wq, float* __restrict__ bq)
{
    int i = blockIdx.x * blockDim.x + threadIdx.x;   // D * 448
    int k = i / 448, n = (i - k * 448) * 8;
    const float* sp;
    if (n < 1024)      sp = qw  + k * 1024 + n;
    else if (n < 2048) sp = kw  + k * 1024 + (n - 1024);
    else if (n < 3072) sp = vw  + k * 1024 + (n - 2048);
    else               sp = mw1 + k * 512  + (n - 3072);
    float4 a = *(const float4*)sp;
    float4 b = *(const float4*)(sp + 4);
    *(uint4*)&wq[(size_t)k * NQKV + n] =
        make_uint4(h2bits(a.x, a.y), h2bits(a.z, a.w), h2bits(b.x, b.y), h2bits(b.z, b.w));
    if (i < NQKV) {
        float bb;
        if (i < 1024)      bb = qb[i];
        else if (i < 2048) bb = kb[i - 1024];
        else if (i < 3072) bb = vb[i - 2048];
        else               bb = mb1[i - 3072];
        bq[i] = bb;
    }
}

// mech[r] = sigmoid(dot(qkv16[r, 3072:3584], mw2) + mb2); one warp per row.
__global__ void mech_out_k(const __half* __restrict__ qkv, const float* __restrict__ mw2,
                           const float* __restrict__ mb2, float* __restrict__ mech,
                           float* __restrict__ out_mech)
{
    int row  = blockIdx.x * 8 + (threadIdx.x >> 5);
    int lane = threadIdx.x & 31;
    const __half* r = qkv + (size_t)row * NQKV + 3072;
    float s = 0.f;
#pragma unroll
    for (int c = lane; c < 512; c += 32) s = fmaf(__half2float(r[c]), mw2[c], s);
#pragma unroll
    for (int off = 16; off > 0; off >>= 1) s += __shfl_xor_sync(0xffffffffu, s, off);
    if (lane == 0) {
        float t = s + mb2[0];
        float m = 1.f / (1.f + expf(-t));
        mech[row] = m;
        out_mech[row] = m;
    }
}

// ---------------------------------------------------------------------------
// Host launcher
// ---------------------------------------------------------------------------
extern "C" void kernel_launch(void* const* d_in, const int* in_sizes, int n_in,
                              void* d_out, int out_size)
{
    (void)in_sizes; (void)n_in; (void)out_size;
    const float* x_in = (const float*)d_in[0];
    const float* pos  = (const float*)d_in[1];
    const float* tim  = (const float*)d_in[2];
    const float* wi   = (const float*)d_in[3];
    const float* bi   = (const float*)d_in[4];
    const float* g1   = (const float*)d_in[5];
    const float* be1  = (const float*)d_in[6];
    const float* g2   = (const float*)d_in[7];
    const float* be2  = (const float*)d_in[8];
    const float* g3   = (const float*)d_in[9];
    const float* be3  = (const float*)d_in[10];
    const float* qw   = (const float*)d_in[11];
    const float* qb   = (const float*)d_in[12];
    const float* kw   = (const float*)d_in[13];
    const float* kb   = (const float*)d_in[14];
    const float* vw   = (const float*)d_in[15];
    const float* vb   = (const float*)d_in[16];
    const float* ow   = (const float*)d_in[17];
    const float* ob   = (const float*)d_in[18];
    const float* mw1  = (const float*)d_in[19];
    const float* mb1  = (const float*)d_in[20];
    const float* mw2  = (const float*)d_in[21];
    const float* mb2  = (const float*)d_in[22];
    const float* ew   = (const float*)d_in[23];
    const float* eb   = (const float*)d_in[24];
    const float* elw  = (const float*)d_in[25];
    const float* fw1  = (const float*)d_in[26];
    const float* fb1  = (const float*)d_in[27];
    const float* fw2  = (const float*)d_in[28];
    const float* fb2  = (const float*)d_in[29];

    float* out = (float*)d_out;
    float* out_mech = out + NXD;
    float* out_w    = out + NXD + BS;

    float* fb = nullptr;
    cudaGetSymbolAddress((void**)&fb, g_buf);
    float* gx    = fb + OFF_X;
    float* gpep  = fb + OFF_PEP;
    float* gmech = fb + OFF_MECH;
    float* gb5   = fb + OFF_B5;
    float* gwsm  = fb + OFF_WSM;
    float* gbqkv = fb + OFF_BQKV;

    __half *h16, *qkv16, *ctx16, *ffh16, *pe16, *w16;
    cudaGetSymbolAddress((void**)&h16,   g_h16);
    cudaGetSymbolAddress((void**)&qkv16, g_qkv16);
    cudaGetSymbolAddress((void**)&ctx16, g_ctx16);
    cudaGetSymbolAddress((void**)&ffh16, g_ffh16);
    cudaGetSymbolAddress((void**)&pe16,  g_pe16);
    cudaGetSymbolAddress((void**)&w16,   g_w16);

    const int GEMM_SMEM = 98304;   // 3 x 32KB stages
    cudaFuncSetAttribute(hgemm_k, cudaFuncAttributeMaxDynamicSharedMemorySize, GEMM_SMEM);
    const int ATTN_SMEM = 49664;
    cudaFuncSetAttribute(attn_h_k, cudaFuncAttributeMaxDynamicSharedMemorySize, ATTN_SMEM);

    // weight conversions (fp32 -> fp16), single fused launch + QKV pack
    cvtall_k<<<(10 * 1024 * 1024 / 8) / 256, 256>>>(wi, ow, fw1, fw2, w16);
    pack_qkvm_k<<<(Dc * 448) / 256, 256>>>(qw, kw, vw, mw1, qb, kb, vb, mb1,
                                           w16 + W16_QKV, gbqkv);

    // 1) positional/timing embedding
    build_pe_k<<<(Sc * Dc / 4) / 256, 256>>>(pos, tim, pe16);
    hgemm_k<<<dim3(Dc / 128, Sc / 128), 256, GEMM_SMEM>>>(pe16, w16 + W16_WI, bi, nullptr,
                                                          gpep, Sc, Dc, Dc, 0, 0);
    // 2) x = x_in + pep; norm1 -> h16  (fused)
    ln_addpe_k<<<BS, 256>>>(x_in, gpep, g1, be1, gx, h16);

    // 3) fused QKV + mech-hidden projection (fp16 out)
    hgemm_k<<<dim3(NQKV / 128, BS / 128), 256, GEMM_SMEM>>>(h16, w16 + W16_QKV, gbqkv,
                                                            nullptr, qkv16, BS, NQKV, Dc, 2, 1);

    // 4) mechanism output
    mech_out_k<<<BS / 8, 256>>>(qkv16, mw2, mb2, gmech, out_mech);

    // 5) fp16 flash attention -> ctx16
    attn_h_k<<<dim3(Sc / 128, Bc * Hc), 256, ATTN_SMEM>>>(qkv16, gmech, ctx16);

    // 6) output projection + residual
    hgemm_k<<<dim3(Dc / 128, BS / 128), 256, GEMM_SMEM>>>(ctx16, w16 + W16_OW, ob, gx,
                                                          gx, BS, Dc, Dc, 0, 0);

    // 7) five elements (folded to one GEMM)
    layernorm_k<<<BS, 256>>>(gx, g2, be2, h16);
    softmax5_k<<<1, 32>>>(elw, gwsm, out_w);
    combine_w5_k<<<(Dc * Dc / 4) / 256, 256>>>(ew, gwsm, w16 + W16_W5);
    combine_b5_k<<<Dc / 256, 256>>>(eb, gwsm, gb5);
    hgemm_k<<<dim3(Dc / 128, BS / 128), 256, GEMM_SMEM>>>(h16, w16 + W16_W5, gb5, gx,
                                                          gx, BS, Dc, Dc, 0, 0);

    // 8) FFN
    layernorm_k<<<BS, 256>>>(gx, g3, be3, h16);
    hgemm_k<<<dim3(DFFc / 128, BS / 128), 256, GEMM_SMEM>>>(h16, w16 + W16_FW1, fb1, nullptr,
                                                            ffh16, BS, DFFc, Dc, 1, 1);
    hgemm_k<<<dim3(Dc / 128, BS / 128), 256, GEMM_SMEM>>>(ffh16, w16 + W16_FW2, fb2, gx,
                                                          out, BS, Dc, DFFc, 0, 0);
}